// round 11
// baseline (speedup 1.0000x reference)
#include <cuda_runtime.h>
#include <cuda_bf16.h>
#include <cstdint>

#define NN 50000
#define EE 800000
#define HID 256
#define HEADS 8
#define CPH 32
#define EDIM 64

// ---------------- scratch ----------------
__device__ __nv_bfloat16  g_xpb [(size_t)NN * HID];  // x @ W (bf16, messages only)
__device__ float          g_ea  [(size_t)EE * HEADS];
__device__ float          g_asrc[(size_t)NN * HEADS];
__device__ float          g_adst[(size_t)NN * HEADS];
__device__ float          g_watt[EDIM * HEADS];
__device__ int            g_deg [NN];
__device__ int            g_start[NN];
__device__ int            g_cur [NN];
__device__ int            g_csr_src[EE];
__device__ int            g_total;
__device__ __nv_bfloat16  g_whi[HID * HID];   // [n][k] = W[k][n]
__device__ __nv_bfloat16  g_wlo[HID * HID];

// ------------- init: zero deg counters + fold W_e with att_edge ------------
#define ZBLOCKS 196
__global__ void init_misc(const float* __restrict__ W_e,
                          const float* __restrict__ att_edge) {
    if (blockIdx.x < ZBLOCKS) {
        int i = blockIdx.x * 256 + threadIdx.x;
        if (i < NN) g_deg[i] = 0;
        if (i == 0) g_total = 0;
    } else {
        // 512 entries, 256 threads -> 2 each
        #pragma unroll
        for (int r = 0; r < 2; r++) {
            int i = threadIdx.x + r * 256;
            int d = i >> 3, h = i & 7;
            float s = 0.f;
            #pragma unroll
            for (int c = 0; c < CPH; c++)
                s += W_e[d * (HEADS * CPH) + h * CPH + c] * att_edge[h * CPH + c];
            g_watt[d * HEADS + h] = s;
        }
    }
}

// ---------------- CSR build ----------------
__global__ void count_deg(const int* __restrict__ ei) {
    int e = blockIdx.x * blockDim.x + threadIdx.x;
    if (e < EE) atomicAdd(&g_deg[ei[EE + e]], 1);
}

__global__ void reserve_csr() {
    int n = blockIdx.x * blockDim.x + threadIdx.x;
    int lane = threadIdx.x & 31;
    int d = (n < NN) ? g_deg[n] : 0;
    int incl = d;
    #pragma unroll
    for (int o = 1; o < 32; o <<= 1) {
        int v = __shfl_up_sync(0xffffffffu, incl, o);
        if (lane >= o) incl += v;
    }
    int wtotal = __shfl_sync(0xffffffffu, incl, 31);
    int base = 0;
    if (lane == 31) base = atomicAdd(&g_total, wtotal);
    base = __shfl_sync(0xffffffffu, base, 31);
    int start = base + incl - d;
    if (n < NN) { g_start[n] = start; g_cur[n] = start; }
}

// ---------------- W fp32 -> bf16 hi/lo (transposed) ----------------
__global__ void convert_w(const float* __restrict__ W) {
    int i = blockIdx.x * blockDim.x + threadIdx.x;  // 65536
    if (i >= HID * HID) return;
    int n = i >> 8, k = i & 255;
    float v = W[k * HID + n];                        // transpose: B[n][k] = W[k][n]
    __nv_bfloat16 hi = __float2bfloat16(v);
    g_whi[i] = hi;
    g_wlo[i] = __float2bfloat16(v - __bfloat162float(hi));
}

// ================ mma.sync bf16 GEMM (fused x-split, fused node_att) =======
__device__ __forceinline__ void ldsm_x4(uint32_t addr, uint32_t& r0, uint32_t& r1,
                                        uint32_t& r2, uint32_t& r3) {
    asm volatile("ldmatrix.sync.aligned.m8n8.x4.shared.b16 {%0,%1,%2,%3}, [%4];"
                 : "=r"(r0), "=r"(r1), "=r"(r2), "=r"(r3) : "r"(addr));
}
__device__ __forceinline__ void mma_bf16(float* c, const uint32_t* a,
                                         uint32_t b0, uint32_t b1) {
    asm volatile(
        "mma.sync.aligned.m16n8k16.row.col.f32.bf16.bf16.f32 "
        "{%0,%1,%2,%3}, {%4,%5,%6,%7}, {%8,%9}, {%0,%1,%2,%3};"
        : "+f"(c[0]), "+f"(c[1]), "+f"(c[2]), "+f"(c[3])
        : "r"(a[0]), "r"(a[1]), "r"(a[2]), "r"(a[3]), "r"(b0), "r"(b1));
}
__device__ __forceinline__ uint32_t smem_u32(const void* p) {
    uint32_t a;
    asm("{ .reg .u64 t; cvta.to.shared.u64 t, %1; cvt.u32.u64 %0, t; }"
        : "=r"(a) : "l"(p));
    return a;
}
__device__ __forceinline__ uint32_t pack_bf16x2(float a, float b) {
    __nv_bfloat162 p;
    p.x = __float2bfloat16(a);
    p.y = __float2bfloat16(b);
    return *(uint32_t*)&p;
}

// SMEM layout (dynamic): swizzled tiles, 128B rows of 8x16B chunks
#define SM_AHI  0
#define SM_ALO  16384
#define SM_BHI  32768
#define SM_BLO  40960
#define SM_ATTS 49152
#define SM_ATTD 49408
#define SM_SZ   49664
#define SWO(row, c) ((uint32_t)((row) * 128 + (((c) ^ ((row) & 7)) << 4)))

__global__ __launch_bounds__(256, 2) void gemm_mma(const float* __restrict__ x,
                                                   const float* __restrict__ att_src,
                                                   const float* __restrict__ att_dst) {
    extern __shared__ char smem[];
    uint32_t sb = smem_u32(smem);
    int tid = threadIdx.x;
    int wid = tid >> 5;
    int lane = tid & 31;
    int bm = blockIdx.y * 128;
    int bn = blockIdx.x * 64;
    int mrow0 = (wid & 3) * 32;
    int ncol0 = (wid >> 2) * 32;

    float* satts = (float*)(smem + SM_ATTS);
    float* sattd = (float*)(smem + SM_ATTD);
    if (tid < 64) {
        satts[tid] = att_src[bn + tid];
        sattd[tid] = att_dst[bn + tid];
    }

    float acc[2][4][4];
    #pragma unroll
    for (int ma = 0; ma < 2; ma++)
        #pragma unroll
        for (int nb = 0; nb < 4; nb++)
            #pragma unroll
            for (int j = 0; j < 4; j++) acc[ma][nb][j] = 0.f;

    // per-thread A-staging coords: 1024 chunks (128 rows x 8 chunks), 4/thread
    #pragma unroll 1
    for (int kc = 0; kc < 4; kc++) {
        // ---- stage A from fp32 x, split hi/lo in-kernel ----
        #pragma unroll
        for (int j = 0; j < 4; j++) {
            int i = tid + j * 256;
            int row = i >> 3, c = i & 7;     // chunk c = 8 k-values
            uint32_t off = SWO(row, c);
            int rg = bm + row;
            uint4 vh = make_uint4(0, 0, 0, 0), vl = make_uint4(0, 0, 0, 0);
            if (rg < NN) {
                const float4* p = (const float4*)(x + ((size_t)rg << 8) + kc * 64 + c * 8);
                float4 f0 = p[0], f1 = p[1];
                vh.x = pack_bf16x2(f0.x, f0.y);
                vh.y = pack_bf16x2(f0.z, f0.w);
                vh.z = pack_bf16x2(f1.x, f1.y);
                vh.w = pack_bf16x2(f1.z, f1.w);
                __nv_bfloat162* hb;
                hb = (__nv_bfloat162*)&vh.x;
                vl.x = pack_bf16x2(f0.x - __bfloat162float(hb->x), f0.y - __bfloat162float(hb->y));
                hb = (__nv_bfloat162*)&vh.y;
                vl.y = pack_bf16x2(f0.z - __bfloat162float(hb->x), f0.w - __bfloat162float(hb->y));
                hb = (__nv_bfloat162*)&vh.z;
                vl.z = pack_bf16x2(f1.x - __bfloat162float(hb->x), f1.y - __bfloat162float(hb->y));
                hb = (__nv_bfloat162*)&vh.w;
                vl.w = pack_bf16x2(f1.z - __bfloat162float(hb->x), f1.w - __bfloat162float(hb->y));
            }
            *(uint4*)(smem + SM_AHI + off) = vh;
            *(uint4*)(smem + SM_ALO + off) = vl;
        }
        // ---- stage B (64x64, hi+lo), rows are n, cols are k ----
        #pragma unroll
        for (int j = 0; j < 2; j++) {
            int i = tid + j * 256;
            int n = i >> 3, c = i & 7;
            uint32_t off = SWO(n, c);
            const __nv_bfloat16* ph = g_whi + ((size_t)(bn + n) << 8) + kc * 64 + c * 8;
            const __nv_bfloat16* pl = g_wlo + ((size_t)(bn + n) << 8) + kc * 64 + c * 8;
            *(uint4*)(smem + SM_BHI + off) = *(const uint4*)ph;
            *(uint4*)(smem + SM_BLO + off) = *(const uint4*)pl;
        }
        __syncthreads();

        #pragma unroll
        for (int ks = 0; ks < 4; ks++) {
            uint32_t ahi[2][4], alo[2][4];
            #pragma unroll
            for (int ma = 0; ma < 2; ma++) {
                int row = mrow0 + ma * 16 + (lane & 15);
                int c = ks * 2 + (lane >> 4);
                uint32_t off = SWO(row, c);
                ldsm_x4(sb + SM_AHI + off, ahi[ma][0], ahi[ma][1], ahi[ma][2], ahi[ma][3]);
                ldsm_x4(sb + SM_ALO + off, alo[ma][0], alo[ma][1], alo[ma][2], alo[ma][3]);
            }
            uint32_t bhi[4][2], blo[4][2];
            #pragma unroll
            for (int nb2 = 0; nb2 < 2; nb2++) {
                int n = ncol0 + nb2 * 16 + (lane & 7) + ((lane & 16) >> 1);
                int c = ks * 2 + ((lane >> 3) & 1);
                uint32_t off = SWO(n, c);
                ldsm_x4(sb + SM_BHI + off, bhi[nb2 * 2][0], bhi[nb2 * 2][1],
                        bhi[nb2 * 2 + 1][0], bhi[nb2 * 2 + 1][1]);
                ldsm_x4(sb + SM_BLO + off, blo[nb2 * 2][0], blo[nb2 * 2][1],
                        blo[nb2 * 2 + 1][0], blo[nb2 * 2 + 1][1]);
            }
            #pragma unroll
            for (int ma = 0; ma < 2; ma++)
                #pragma unroll
                for (int nb = 0; nb < 4; nb++) {
                    mma_bf16(acc[ma][nb], ahi[ma], bhi[nb][0], bhi[nb][1]);
                    mma_bf16(acc[ma][nb], ahi[ma], blo[nb][0], blo[nb][1]);
                    mma_bf16(acc[ma][nb], alo[ma], bhi[nb][0], bhi[nb][1]);
                }
        }
        __syncthreads();
    }

    // ---- epilogue: store xp (bf16) + fused a_src/a_dst (one head per warp) ----
    int head = (bn + ncol0) >> 5;
    #pragma unroll
    for (int ma = 0; ma < 2; ma++) {
        int row0 = bm + mrow0 + ma * 16 + (lane >> 2);
        int row1 = row0 + 8;
        float ps0 = 0.f, pd0 = 0.f, ps1 = 0.f, pd1 = 0.f;
        #pragma unroll
        for (int nb = 0; nb < 4; nb++) {
            int colt = ncol0 + nb * 8 + (lane & 3) * 2;   // col within 64-tile
            float c0 = acc[ma][nb][0], c1 = acc[ma][nb][1];
            float c2 = acc[ma][nb][2], c3 = acc[ma][nb][3];
            if (row0 < NN) {
                __nv_bfloat162 p; p.x = __float2bfloat16(c0); p.y = __float2bfloat16(c1);
                *(__nv_bfloat162*)(g_xpb + (size_t)row0 * HID + bn + colt) = p;
            }
            if (row1 < NN) {
                __nv_bfloat162 p; p.x = __float2bfloat16(c2); p.y = __float2bfloat16(c3);
                *(__nv_bfloat162*)(g_xpb + (size_t)row1 * HID + bn + colt) = p;
            }
            float as0 = satts[colt], as1 = satts[colt + 1];
            float ad0 = sattd[colt], ad1 = sattd[colt + 1];
            ps0 += c0 * as0 + c1 * as1;
            pd0 += c0 * ad0 + c1 * ad1;
            ps1 += c2 * as0 + c3 * as1;
            pd1 += c2 * ad0 + c3 * ad1;
        }
        #pragma unroll
        for (int o = 1; o <= 2; o <<= 1) {
            ps0 += __shfl_xor_sync(0xffffffffu, ps0, o);
            pd0 += __shfl_xor_sync(0xffffffffu, pd0, o);
            ps1 += __shfl_xor_sync(0xffffffffu, ps1, o);
            pd1 += __shfl_xor_sync(0xffffffffu, pd1, o);
        }
        if ((lane & 3) == 0) {
            if (row0 < NN) {
                g_asrc[(size_t)row0 * HEADS + head] = ps0;
                g_adst[(size_t)row0 * HEADS + head] = pd0;
            }
            if (row1 < NN) {
                g_asrc[(size_t)row1 * HEADS + head] = ps1;
                g_adst[(size_t)row1 * HEADS + head] = pd1;
            }
        }
    }
}

// -------- edge pass: logits -> leakyrelu -> exp + fused CSR scatter --------
__global__ __launch_bounds__(256) void edge_ea(const int* __restrict__ ei,
                                               const float* __restrict__ eattr) {
    __shared__ float4 ws4[EDIM * 2];       // [d*2] = heads0-3, [d*2+1] = heads4-7
    for (int i = threadIdx.x; i < EDIM * 2; i += blockDim.x)
        ws4[i] = ((const float4*)g_watt)[i];
    __syncthreads();
    int e = blockIdx.x * blockDim.x + threadIdx.x;
    if (e >= EE) return;
    int src = ei[e];
    int dst = ei[EE + e];

    const float4* as4 = (const float4*)(g_asrc + (size_t)src * HEADS);
    const float4* ad4 = (const float4*)(g_adst + (size_t)dst * HEADS);
    float4 as0 = as4[0], as1 = as4[1];
    float4 ad0 = ad4[0], ad1 = ad4[1];

    float4 accA = make_float4(0.f, 0.f, 0.f, 0.f);
    float4 accB = make_float4(0.f, 0.f, 0.f, 0.f);

    const float4* ea4 = (const float4*)(eattr + (size_t)e * EDIM);
    #pragma unroll
    for (int d4 = 0; d4 < EDIM / 4; d4++) {
        float4 v = ea4[d4];
        int d = d4 * 4;
        float4 w;
        w = ws4[(d + 0) * 2];     accA.x += v.x * w.x; accA.y += v.x * w.y; accA.z += v.x * w.z; accA.w += v.x * w.w;
        w = ws4[(d + 0) * 2 + 1]; accB.x += v.x * w.x; accB.y += v.x * w.y; accB.z += v.x * w.z; accB.w += v.x * w.w;
        w = ws4[(d + 1) * 2];     accA.x += v.y * w.x; accA.y += v.y * w.y; accA.z += v.y * w.z; accA.w += v.y * w.w;
        w = ws4[(d + 1) * 2 + 1]; accB.x += v.y * w.x; accB.y += v.y * w.y; accB.z += v.y * w.z; accB.w += v.y * w.w;
        w = ws4[(d + 2) * 2];     accA.x += v.z * w.x; accA.y += v.z * w.y; accA.z += v.z * w.z; accA.w += v.z * w.w;
        w = ws4[(d + 2) * 2 + 1]; accB.x += v.z * w.x; accB.y += v.z * w.y; accB.z += v.z * w.z; accB.w += v.z * w.w;
        w = ws4[(d + 3) * 2];     accA.x += v.w * w.x; accA.y += v.w * w.y; accA.z += v.w * w.z; accA.w += v.w * w.w;
        w = ws4[(d + 3) * 2 + 1]; accB.x += v.w * w.x; accB.y += v.w * w.y; accB.z += v.w * w.z; accB.w += v.w * w.w;
    }

    float a[HEADS];
    a[0] = as0.x + ad0.x + accA.x;
    a[1] = as0.y + ad0.y + accA.y;
    a[2] = as0.z + ad0.z + accA.z;
    a[3] = as0.w + ad0.w + accA.w;
    a[4] = as1.x + ad1.x + accB.x;
    a[5] = as1.y + ad1.y + accB.y;
    a[6] = as1.z + ad1.z + accB.z;
    a[7] = as1.w + ad1.w + accB.w;

    #pragma unroll
    for (int h = 0; h < HEADS; h++) {
        float al = a[h];
        al = (al > 0.f) ? al : 0.2f * al;   // LeakyReLU
        a[h] = __expf(al);                  // softmax is shift-invariant
    }
    int pos = atomicAdd(&g_cur[dst], 1);    // fused CSR slot reservation
    g_csr_src[pos] = src;
    float4* out = (float4*)(g_ea + (size_t)pos * HEADS);
    out[0] = make_float4(a[0], a[1], a[2], a[3]);
    out[1] = make_float4(a[4], a[5], a[6], a[7]);
}

// -------- aggregate: 1 warp/node, shuffle-free, bf16 gather, LN ------------
__global__ __launch_bounds__(256) void aggregate(const float* __restrict__ x,
                                                 const float* __restrict__ bias,
                                                 const float* __restrict__ gamma,
                                                 const float* __restrict__ beta,
                                                 float* __restrict__ out) {
    int node = blockIdx.x * 8 + (threadIdx.x >> 5);
    int lane = threadIdx.x & 31;
    if (node >= NN) return;
    int start = g_start[node];
    int deg   = g_deg[node];
    int myhead = lane >> 2;          // channels lane*8 .. lane*8+7 all in this head

    const float* eap = g_ea + (size_t)start * HEADS + myhead;
    const int*   srp = g_csr_src + start;

    float accf[8];
    #pragma unroll
    for (int k = 0; k < 8; k++) accf[k] = 0.f;
    float den = 0.f;

    int i = 0;
    for (; i + 2 <= deg; i += 2) {
        int s0 = srp[i], s1 = srp[i + 1];
        float e0 = eap[(size_t)i * HEADS];
        float e1 = eap[(size_t)(i + 1) * HEADS];
        uint4 v0 = *(const uint4*)(g_xpb + (size_t)s0 * HID + lane * 8);
        uint4 v1 = *(const uint4*)(g_xpb + (size_t)s1 * HID + lane * 8);
        den += e0 + e1;
        float2 f;
        f = __bfloat1622float2(*(__nv_bfloat162*)&v0.x); accf[0] += e0 * f.x; accf[1] += e0 * f.y;
        f = __bfloat1622float2(*(__nv_bfloat162*)&v0.y); accf[2] += e0 * f.x; accf[3] += e0 * f.y;
        f = __bfloat1622float2(*(__nv_bfloat162*)&v0.z); accf[4] += e0 * f.x; accf[5] += e0 * f.y;
        f = __bfloat1622float2(*(__nv_bfloat162*)&v0.w); accf[6] += e0 * f.x; accf[7] += e0 * f.y;
        f = __bfloat1622float2(*(__nv_bfloat162*)&v1.x); accf[0] += e1 * f.x; accf[1] += e1 * f.y;
        f = __bfloat1622float2(*(__nv_bfloat162*)&v1.y); accf[2] += e1 * f.x; accf[3] += e1 * f.y;
        f = __bfloat1622float2(*(__nv_bfloat162*)&v1.z); accf[4] += e1 * f.x; accf[5] += e1 * f.y;
        f = __bfloat1622float2(*(__nv_bfloat162*)&v1.w); accf[6] += e1 * f.x; accf[7] += e1 * f.y;
    }
    if (i < deg) {
        int s0 = srp[i];
        float e0 = eap[(size_t)i * HEADS];
        uint4 v0 = *(const uint4*)(g_xpb + (size_t)s0 * HID + lane * 8);
        den += e0;
        float2 f;
        f = __bfloat1622float2(*(__nv_bfloat162*)&v0.x); accf[0] += e0 * f.x; accf[1] += e0 * f.y;
        f = __bfloat1622float2(*(__nv_bfloat162*)&v0.y); accf[2] += e0 * f.x; accf[3] += e0 * f.y;
        f = __bfloat1622float2(*(__nv_bfloat162*)&v0.z); accf[4] += e0 * f.x; accf[5] += e0 * f.y;
        f = __bfloat1622float2(*(__nv_bfloat162*)&v0.w); accf[6] += e0 * f.x; accf[7] += e0 * f.y;
    }

    float inv = 1.f / (den + 1e-16f);   // full per-head den (every lane summed all edges)

    // residual + bias
    const float4* x4 = (const float4*)(x + (size_t)node * HID + lane * 8);
    const float4* b4 = (const float4*)(bias + lane * 8);
    float4 xa = x4[0], xb = x4[1];
    float4 ba = b4[0], bb = b4[1];
    float va[8];
    va[0] = xa.x + accf[0] * inv + ba.x;
    va[1] = xa.y + accf[1] * inv + ba.y;
    va[2] = xa.z + accf[2] * inv + ba.z;
    va[3] = xa.w + accf[3] * inv + ba.w;
    va[4] = xb.x + accf[4] * inv + bb.x;
    va[5] = xb.y + accf[5] * inv + bb.y;
    va[6] = xb.z + accf[6] * inv + bb.z;
    va[7] = xb.w + accf[7] * inv + bb.w;

    float s = 0.f, q = 0.f;
    #pragma unroll
    for (int k = 0; k < 8; k++) { s += va[k]; q += va[k] * va[k]; }
    #pragma unroll
    for (int o = 16; o > 0; o >>= 1) {
        s += __shfl_xor_sync(0xffffffffu, s, o);
        q += __shfl_xor_sync(0xffffffffu, q, o);
    }
    float mu = s * (1.f / HID);
    float var = q * (1.f / HID) - mu * mu;
    float rstd = rsqrtf(var + 1e-5f);

    const float4* g4 = (const float4*)(gamma + lane * 8);
    const float4* e4 = (const float4*)(beta + lane * 8);
    float4 ga = g4[0], gb = g4[1];
    float4 be = e4[0], bf = e4[1];
    float4 oa, ob;
    oa.x = (va[0] - mu) * rstd * ga.x + be.x;
    oa.y = (va[1] - mu) * rstd * ga.y + be.y;
    oa.z = (va[2] - mu) * rstd * ga.z + be.z;
    oa.w = (va[3] - mu) * rstd * ga.w + be.w;
    ob.x = (va[4] - mu) * rstd * gb.x + bf.x;
    ob.y = (va[5] - mu) * rstd * gb.y + bf.y;
    ob.z = (va[6] - mu) * rstd * gb.z + bf.z;
    ob.w = (va[7] - mu) * rstd * gb.w + bf.w;

    float4* o4 = (float4*)(out + (size_t)node * HID + lane * 8);
    o4[0] = oa;
    o4[1] = ob;
}

// ---------------- launch ----------------
extern "C" void kernel_launch(void* const* d_in, const int* in_sizes, int n_in,
                              void* d_out, int out_size) {
    const float* x        = (const float*)d_in[0];
    const int*   ei       = (const int*)  d_in[1];
    const float* eattr    = (const float*)d_in[2];
    const float* W        = (const float*)d_in[3];
    const float* W_e      = (const float*)d_in[4];
    const float* att_src  = (const float*)d_in[5];
    const float* att_dst  = (const float*)d_in[6];
    const float* att_edge = (const float*)d_in[7];
    const float* bias     = (const float*)d_in[8];
    const float* gamma    = (const float*)d_in[9];
    const float* beta     = (const float*)d_in[10];
    float* out = (float*)d_out;

    cudaFuncSetAttribute(gemm_mma, cudaFuncAttributeMaxDynamicSharedMemorySize, SM_SZ);

    init_misc<<<ZBLOCKS + 1, 256>>>(W_e, att_edge);
    count_deg<<<(EE + 255) / 256, 256>>>(ei);
    reserve_csr<<<(NN + 255) / 256, 256>>>();

    convert_w<<<(HID * HID + 255) / 256, 256>>>(W);

    dim3 ggrid(HID / 64, (NN + 127) / 128);
    gemm_mma<<<ggrid, 256, SM_SZ>>>(x, att_src, att_dst);

    edge_ea<<<(EE + 255) / 256, 256>>>(ei, eattr);
    aggregate<<<(NN + 7) / 8, 256>>>(x, bias, gamma, beta, out);
}

// round 12
// speedup vs baseline: 1.0777x; 1.0777x over previous
#include <cuda_runtime.h>
#include <cuda_bf16.h>
#include <cstdint>

#define NN 50000
#define EE 800000
#define HID 256
#define HEADS 8
#define CPH 32
#define EDIM 64

// ---------------- scratch ----------------
__device__ __nv_bfloat16  g_xpb [(size_t)NN * HID];  // x @ W (bf16, messages only)
__device__ float          g_ea  [(size_t)EE * HEADS];
__device__ float          g_asrc[(size_t)NN * HEADS];
__device__ float          g_adst[(size_t)NN * HEADS];
__device__ float          g_watt[EDIM * HEADS];
__device__ int            g_deg [NN];
__device__ int            g_start[NN];
__device__ int            g_cur [NN];
__device__ int            g_csr_src[EE];
__device__ int            g_total;
__device__ __nv_bfloat16  g_xhi[(size_t)NN * HID];
__device__ __nv_bfloat16  g_xlo[(size_t)NN * HID];
__device__ __nv_bfloat16  g_whi[HID * HID];   // [n][k] = W[k][n]
__device__ __nv_bfloat16  g_wlo[HID * HID];

// ---------------- zero counters ----------------
__global__ void zero_deg() {
    int i = blockIdx.x * blockDim.x + threadIdx.x;
    if (i < NN) g_deg[i] = 0;
    if (i == 0) g_total = 0;
}

// ---------------- fold W_e with att_edge ----------------
__global__ void compute_watt(const float* __restrict__ W_e,
                             const float* __restrict__ att_edge) {
    int i = threadIdx.x;              // 512 threads
    int d = i >> 3, h = i & 7;
    float s = 0.f;
    #pragma unroll
    for (int c = 0; c < CPH; c++)
        s += W_e[d * (HEADS * CPH) + h * CPH + c] * att_edge[h * CPH + c];
    g_watt[d * HEADS + h] = s;
}

// ---------------- CSR build ----------------
__global__ void count_deg(const int* __restrict__ ei) {
    int e = blockIdx.x * blockDim.x + threadIdx.x;
    if (e < EE) atomicAdd(&g_deg[ei[EE + e]], 1);
}

__global__ void reserve_csr() {
    int n = blockIdx.x * blockDim.x + threadIdx.x;
    int lane = threadIdx.x & 31;
    int d = (n < NN) ? g_deg[n] : 0;
    int incl = d;
    #pragma unroll
    for (int o = 1; o < 32; o <<= 1) {
        int v = __shfl_up_sync(0xffffffffu, incl, o);
        if (lane >= o) incl += v;
    }
    int wtotal = __shfl_sync(0xffffffffu, incl, 31);
    int base = 0;
    if (lane == 31) base = atomicAdd(&g_total, wtotal);
    base = __shfl_sync(0xffffffffu, base, 31);
    int start = base + incl - d;
    if (n < NN) { g_start[n] = start; g_cur[n] = start; }
}

// ---------------- fp32 -> bf16 hi/lo split ----------------
__global__ void convert_x(const float* __restrict__ x) {
    size_t i = ((size_t)blockIdx.x * blockDim.x + threadIdx.x) * 4;
    if (i >= (size_t)NN * HID) return;
    float4 v = *(const float4*)(x + i);
    __nv_bfloat16 h0 = __float2bfloat16(v.x);
    __nv_bfloat16 h1 = __float2bfloat16(v.y);
    __nv_bfloat16 h2 = __float2bfloat16(v.z);
    __nv_bfloat16 h3 = __float2bfloat16(v.w);
    __nv_bfloat162 hi0; hi0.x = h0; hi0.y = h1;
    __nv_bfloat162 hi1; hi1.x = h2; hi1.y = h3;
    __nv_bfloat162 lo0, lo1;
    lo0.x = __float2bfloat16(v.x - __bfloat162float(h0));
    lo0.y = __float2bfloat16(v.y - __bfloat162float(h1));
    lo1.x = __float2bfloat16(v.z - __bfloat162float(h2));
    lo1.y = __float2bfloat16(v.w - __bfloat162float(h3));
    *(__nv_bfloat162*)(g_xhi + i)     = hi0;
    *(__nv_bfloat162*)(g_xhi + i + 2) = hi1;
    *(__nv_bfloat162*)(g_xlo + i)     = lo0;
    *(__nv_bfloat162*)(g_xlo + i + 2) = lo1;
}

__global__ void convert_w(const float* __restrict__ W) {
    int i = blockIdx.x * blockDim.x + threadIdx.x;  // 65536
    if (i >= HID * HID) return;
    int n = i >> 8, k = i & 255;
    float v = W[k * HID + n];                        // transpose: B[n][k] = W[k][n]
    __nv_bfloat16 hi = __float2bfloat16(v);
    g_whi[i] = hi;
    g_wlo[i] = __float2bfloat16(v - __bfloat162float(hi));
}

// ================ mma.sync bf16 GEMM (compute_103-legal tensor path) =======
__device__ __forceinline__ void ldsm_x4(uint32_t addr, uint32_t& r0, uint32_t& r1,
                                        uint32_t& r2, uint32_t& r3) {
    asm volatile("ldmatrix.sync.aligned.m8n8.x4.shared.b16 {%0,%1,%2,%3}, [%4];"
                 : "=r"(r0), "=r"(r1), "=r"(r2), "=r"(r3) : "r"(addr));
}
__device__ __forceinline__ void mma_bf16(float* c, const uint32_t* a,
                                         uint32_t b0, uint32_t b1) {
    asm volatile(
        "mma.sync.aligned.m16n8k16.row.col.f32.bf16.bf16.f32 "
        "{%0,%1,%2,%3}, {%4,%5,%6,%7}, {%8,%9}, {%0,%1,%2,%3};"
        : "+f"(c[0]), "+f"(c[1]), "+f"(c[2]), "+f"(c[3])
        : "r"(a[0]), "r"(a[1]), "r"(a[2]), "r"(a[3]), "r"(b0), "r"(b1));
}
__device__ __forceinline__ uint32_t smem_u32(const void* p) {
    uint32_t a;
    asm("{ .reg .u64 t; cvta.to.shared.u64 t, %1; cvt.u32.u64 %0, t; }"
        : "=r"(a) : "l"(p));
    return a;
}

// SMEM layout (dynamic): swizzled tiles, 128B rows of 8x16B chunks
#define SM_AHI  0
#define SM_ALO  16384
#define SM_BHI  32768
#define SM_BLO  40960
#define SM_ATTS 49152
#define SM_ATTD 49408
#define SM_SZ   49664
#define SWO(row, c) ((uint32_t)((row) * 128 + (((c) ^ ((row) & 7)) << 4)))

__global__ __launch_bounds__(256, 2) void gemm_mma(const float* __restrict__ att_src,
                                                   const float* __restrict__ att_dst) {
    extern __shared__ char smem[];
    uint32_t sb = smem_u32(smem);
    int tid = threadIdx.x;
    int wid = tid >> 5;
    int lane = tid & 31;
    int bm = blockIdx.y * 128;
    int bn = blockIdx.x * 64;
    int mrow0 = (wid & 3) * 32;
    int ncol0 = (wid >> 2) * 32;

    float* satts = (float*)(smem + SM_ATTS);
    float* sattd = (float*)(smem + SM_ATTD);
    if (tid < 64) {
        satts[tid] = att_src[bn + tid];
        sattd[tid] = att_dst[bn + tid];
    }

    float acc[2][4][4];
    #pragma unroll
    for (int ma = 0; ma < 2; ma++)
        #pragma unroll
        for (int nb = 0; nb < 4; nb++)
            #pragma unroll
            for (int j = 0; j < 4; j++) acc[ma][nb][j] = 0.f;

    #pragma unroll 1
    for (int kc = 0; kc < 4; kc++) {
        // ---- stage A (128x64, hi+lo) ----
        #pragma unroll
        for (int j = 0; j < 4; j++) {
            int i = tid + j * 256;
            int row = i >> 3, c = i & 7;
            uint32_t off = SWO(row, c);
            int rg = bm + row;
            uint4 vh = make_uint4(0, 0, 0, 0), vl = make_uint4(0, 0, 0, 0);
            if (rg < NN) {
                const __nv_bfloat16* ph = g_xhi + ((size_t)rg << 8) + kc * 64 + c * 8;
                const __nv_bfloat16* pl = g_xlo + ((size_t)rg << 8) + kc * 64 + c * 8;
                vh = *(const uint4*)ph;
                vl = *(const uint4*)pl;
            }
            *(uint4*)(smem + SM_AHI + off) = vh;
            *(uint4*)(smem + SM_ALO + off) = vl;
        }
        // ---- stage B (64x64, hi+lo), rows are n, cols are k ----
        #pragma unroll
        for (int j = 0; j < 2; j++) {
            int i = tid + j * 256;
            int n = i >> 3, c = i & 7;
            uint32_t off = SWO(n, c);
            const __nv_bfloat16* ph = g_whi + ((size_t)(bn + n) << 8) + kc * 64 + c * 8;
            const __nv_bfloat16* pl = g_wlo + ((size_t)(bn + n) << 8) + kc * 64 + c * 8;
            *(uint4*)(smem + SM_BHI + off) = *(const uint4*)ph;
            *(uint4*)(smem + SM_BLO + off) = *(const uint4*)pl;
        }
        __syncthreads();

        #pragma unroll
        for (int ks = 0; ks < 4; ks++) {
            uint32_t ahi[2][4], alo[2][4];
            #pragma unroll
            for (int ma = 0; ma < 2; ma++) {
                int row = mrow0 + ma * 16 + (lane & 15);
                int c = ks * 2 + (lane >> 4);
                uint32_t off = SWO(row, c);
                ldsm_x4(sb + SM_AHI + off, ahi[ma][0], ahi[ma][1], ahi[ma][2], ahi[ma][3]);
                ldsm_x4(sb + SM_ALO + off, alo[ma][0], alo[ma][1], alo[ma][2], alo[ma][3]);
            }
            uint32_t bhi[4][2], blo[4][2];
            #pragma unroll
            for (int nb2 = 0; nb2 < 2; nb2++) {
                int n = ncol0 + nb2 * 16 + (lane & 7) + ((lane & 16) >> 1);
                int c = ks * 2 + ((lane >> 3) & 1);
                uint32_t off = SWO(n, c);
                ldsm_x4(sb + SM_BHI + off, bhi[nb2 * 2][0], bhi[nb2 * 2][1],
                        bhi[nb2 * 2 + 1][0], bhi[nb2 * 2 + 1][1]);
                ldsm_x4(sb + SM_BLO + off, blo[nb2 * 2][0], blo[nb2 * 2][1],
                        blo[nb2 * 2 + 1][0], blo[nb2 * 2 + 1][1]);
            }
            #pragma unroll
            for (int ma = 0; ma < 2; ma++)
                #pragma unroll
                for (int nb = 0; nb < 4; nb++) {
                    mma_bf16(acc[ma][nb], ahi[ma], bhi[nb][0], bhi[nb][1]);
                    mma_bf16(acc[ma][nb], ahi[ma], blo[nb][0], blo[nb][1]);
                    mma_bf16(acc[ma][nb], alo[ma], bhi[nb][0], bhi[nb][1]);
                }
        }
        __syncthreads();
    }

    // ---- epilogue: store xp (bf16) + fused a_src/a_dst (one head per warp) ----
    int head = (bn + ncol0) >> 5;
    #pragma unroll
    for (int ma = 0; ma < 2; ma++) {
        int row0 = bm + mrow0 + ma * 16 + (lane >> 2);
        int row1 = row0 + 8;
        float ps0 = 0.f, pd0 = 0.f, ps1 = 0.f, pd1 = 0.f;
        #pragma unroll
        for (int nb = 0; nb < 4; nb++) {
            int colt = ncol0 + nb * 8 + (lane & 3) * 2;   // col within 64-tile
            float c0 = acc[ma][nb][0], c1 = acc[ma][nb][1];
            float c2 = acc[ma][nb][2], c3 = acc[ma][nb][3];
            if (row0 < NN) {
                __nv_bfloat162 p; p.x = __float2bfloat16(c0); p.y = __float2bfloat16(c1);
                *(__nv_bfloat162*)(g_xpb + (size_t)row0 * HID + bn + colt) = p;
            }
            if (row1 < NN) {
                __nv_bfloat162 p; p.x = __float2bfloat16(c2); p.y = __float2bfloat16(c3);
                *(__nv_bfloat162*)(g_xpb + (size_t)row1 * HID + bn + colt) = p;
            }
            float as0 = satts[colt], as1 = satts[colt + 1];
            float ad0 = sattd[colt], ad1 = sattd[colt + 1];
            ps0 += c0 * as0 + c1 * as1;
            pd0 += c0 * ad0 + c1 * ad1;
            ps1 += c2 * as0 + c3 * as1;
            pd1 += c2 * ad0 + c3 * ad1;
        }
        #pragma unroll
        for (int o = 1; o <= 2; o <<= 1) {
            ps0 += __shfl_xor_sync(0xffffffffu, ps0, o);
            pd0 += __shfl_xor_sync(0xffffffffu, pd0, o);
            ps1 += __shfl_xor_sync(0xffffffffu, ps1, o);
            pd1 += __shfl_xor_sync(0xffffffffu, pd1, o);
        }
        if ((lane & 3) == 0) {
            if (row0 < NN) {
                g_asrc[(size_t)row0 * HEADS + head] = ps0;
                g_adst[(size_t)row0 * HEADS + head] = pd0;
            }
            if (row1 < NN) {
                g_asrc[(size_t)row1 * HEADS + head] = ps1;
                g_adst[(size_t)row1 * HEADS + head] = pd1;
            }
        }
    }
}

// -------- edge pass: smem-staged eattr (coalesced), leakyrelu+exp, scatter --
#define EPB 128   // edges per block (EE % EPB == 0)
__global__ __launch_bounds__(EPB) void edge_ea(const int* __restrict__ ei,
                                               const float* __restrict__ eattr) {
    __shared__ float4 ws4[EDIM * 2];       // [d*2] = heads0-3, [d*2+1] = heads4-7
    __shared__ float4 tile[EPB * 17];      // 16 data f4 + 1 pad per edge row
    int tid = threadIdx.x;
    for (int i = tid; i < EDIM * 2; i += EPB)
        ws4[i] = ((const float4*)g_watt)[i];

    int e0 = blockIdx.x * EPB;
    // stage eattr: EPB edges * 16 float4, fully coalesced global reads
    const float4* gsrc = (const float4*)(eattr + (size_t)e0 * EDIM);
    #pragma unroll
    for (int j = 0; j < 16; j++) {
        int idx = tid + j * EPB;           // 0 .. EPB*16-1
        int er = idx >> 4, c = idx & 15;
        tile[er * 17 + c] = gsrc[idx];
    }
    __syncthreads();

    int e = e0 + tid;
    int src = ei[e];
    int dst = ei[EE + e];

    const float4* as4 = (const float4*)(g_asrc + (size_t)src * HEADS);
    const float4* ad4 = (const float4*)(g_adst + (size_t)dst * HEADS);
    float4 as0 = as4[0], as1 = as4[1];
    float4 ad0 = ad4[0], ad1 = ad4[1];

    float4 accA = make_float4(0.f, 0.f, 0.f, 0.f);
    float4 accB = make_float4(0.f, 0.f, 0.f, 0.f);

    const float4* row = tile + tid * 17;   // conflict-free per 8-lane phase
    #pragma unroll
    for (int d4 = 0; d4 < EDIM / 4; d4++) {
        float4 v = row[d4];
        int d = d4 * 4;
        float4 w;
        w = ws4[(d + 0) * 2];     accA.x += v.x * w.x; accA.y += v.x * w.y; accA.z += v.x * w.z; accA.w += v.x * w.w;
        w = ws4[(d + 0) * 2 + 1]; accB.x += v.x * w.x; accB.y += v.x * w.y; accB.z += v.x * w.z; accB.w += v.x * w.w;
        w = ws4[(d + 1) * 2];     accA.x += v.y * w.x; accA.y += v.y * w.y; accA.z += v.y * w.z; accA.w += v.y * w.w;
        w = ws4[(d + 1) * 2 + 1]; accB.x += v.y * w.x; accB.y += v.y * w.y; accB.z += v.y * w.z; accB.w += v.y * w.w;
        w = ws4[(d + 2) * 2];     accA.x += v.z * w.x; accA.y += v.z * w.y; accA.z += v.z * w.z; accA.w += v.z * w.w;
        w = ws4[(d + 2) * 2 + 1]; accB.x += v.z * w.x; accB.y += v.z * w.y; accB.z += v.z * w.z; accB.w += v.z * w.w;
        w = ws4[(d + 3) * 2];     accA.x += v.w * w.x; accA.y += v.w * w.y; accA.z += v.w * w.z; accA.w += v.w * w.w;
        w = ws4[(d + 3) * 2 + 1]; accB.x += v.w * w.x; accB.y += v.w * w.y; accB.z += v.w * w.z; accB.w += v.w * w.w;
    }

    float a[HEADS];
    a[0] = as0.x + ad0.x + accA.x;
    a[1] = as0.y + ad0.y + accA.y;
    a[2] = as0.z + ad0.z + accA.z;
    a[3] = as0.w + ad0.w + accA.w;
    a[4] = as1.x + ad1.x + accB.x;
    a[5] = as1.y + ad1.y + accB.y;
    a[6] = as1.z + ad1.z + accB.z;
    a[7] = as1.w + ad1.w + accB.w;

    #pragma unroll
    for (int h = 0; h < HEADS; h++) {
        float al = a[h];
        al = (al > 0.f) ? al : 0.2f * al;   // LeakyReLU
        a[h] = __expf(al);                  // softmax is shift-invariant
    }
    int pos = atomicAdd(&g_cur[dst], 1);    // fused CSR slot reservation
    g_csr_src[pos] = src;
    float4* out = (float4*)(g_ea + (size_t)pos * HEADS);
    out[0] = make_float4(a[0], a[1], a[2], a[3]);
    out[1] = make_float4(a[4], a[5], a[6], a[7]);
}

// -------- aggregate: 1 warp/node, batched index loads, bf16 gather, LN ------
__global__ __launch_bounds__(256) void aggregate(const float* __restrict__ x,
                                                 const float* __restrict__ bias,
                                                 const float* __restrict__ gamma,
                                                 const float* __restrict__ beta,
                                                 float* __restrict__ out) {
    int node = blockIdx.x * 8 + (threadIdx.x >> 5);
    int lane = threadIdx.x & 31;
    if (node >= NN) return;
    int start = g_start[node];
    int deg   = g_deg[node];
    int myhead = lane >> 2;          // channels lane*8 .. lane*8+7 are all in this head
    int epair = myhead >> 1;         // ea float2 pair index for my head

    float accf[8];
    #pragma unroll
    for (int k = 0; k < 8; k++) accf[k] = 0.f;
    float2 den2 = make_float2(0.f, 0.f);   // heads (lane&3)*2, +1

    int i0 = 0;
    for (; i0 + 8 <= deg; i0 += 8) {
        int p0 = start + i0;
        int srcs = (lane < 8) ? g_csr_src[p0 + lane] : 0;
        float2 eav = *(const float2*)(g_ea + (size_t)(p0 + (lane >> 2)) * HEADS + (lane & 3) * 2);
        den2.x += eav.x;
        den2.y += eav.y;
        #pragma unroll
        for (int j = 0; j < 8; j++) {
            int src = __shfl_sync(0xffffffffu, srcs, j);
            float ex = __shfl_sync(0xffffffffu, eav.x, j * 4 + epair);
            float ey = __shfl_sync(0xffffffffu, eav.y, j * 4 + epair);
            float eh = (myhead & 1) ? ey : ex;
            uint4 v = *(const uint4*)(g_xpb + (size_t)src * HID + lane * 8);
            float2 f0 = __bfloat1622float2(*(__nv_bfloat162*)&v.x);
            float2 f1 = __bfloat1622float2(*(__nv_bfloat162*)&v.y);
            float2 f2 = __bfloat1622float2(*(__nv_bfloat162*)&v.z);
            float2 f3 = __bfloat1622float2(*(__nv_bfloat162*)&v.w);
            accf[0] += eh * f0.x; accf[1] += eh * f0.y;
            accf[2] += eh * f1.x; accf[3] += eh * f1.y;
            accf[4] += eh * f2.x; accf[5] += eh * f2.y;
            accf[6] += eh * f3.x; accf[7] += eh * f3.y;
        }
    }
    if (i0 < deg) {
        int rem = deg - i0;
        int p0 = start + i0;
        int srcs = (lane < rem && lane < 8) ? g_csr_src[p0 + lane] : 0;
        float2 eav = make_float2(0.f, 0.f);
        if ((lane >> 2) < rem)
            eav = *(const float2*)(g_ea + (size_t)(p0 + (lane >> 2)) * HEADS + (lane & 3) * 2);
        den2.x += eav.x;
        den2.y += eav.y;
        for (int j = 0; j < rem; j++) {
            int src = __shfl_sync(0xffffffffu, srcs, j);
            float ex = __shfl_sync(0xffffffffu, eav.x, j * 4 + epair);
            float ey = __shfl_sync(0xffffffffu, eav.y, j * 4 + epair);
            float eh = (myhead & 1) ? ey : ex;
            uint4 v = *(const uint4*)(g_xpb + (size_t)src * HID + lane * 8);
            float2 f0 = __bfloat1622float2(*(__nv_bfloat162*)&v.x);
            float2 f1 = __bfloat1622float2(*(__nv_bfloat162*)&v.y);
            float2 f2 = __bfloat1622float2(*(__nv_bfloat162*)&v.z);
            float2 f3 = __bfloat1622float2(*(__nv_bfloat162*)&v.w);
            accf[0] += eh * f0.x; accf[1] += eh * f0.y;
            accf[2] += eh * f1.x; accf[3] += eh * f1.y;
            accf[4] += eh * f2.x; accf[5] += eh * f2.y;
            accf[6] += eh * f3.x; accf[7] += eh * f3.y;
        }
    }

    // den: reduce over edge-slot lane bits (2,3,4); lanes grouped by (lane&3)
    #pragma unroll
    for (int o = 4; o < 32; o <<= 1) {
        den2.x += __shfl_xor_sync(0xffffffffu, den2.x, o);
        den2.y += __shfl_xor_sync(0xffffffffu, den2.y, o);
    }
    float dx = __shfl_sync(0xffffffffu, den2.x, epair);  // head myhead&~1
    float dy = __shfl_sync(0xffffffffu, den2.y, epair);  // head myhead|1
    float den = (myhead & 1) ? dy : dx;
    float inv = 1.f / (den + 1e-16f);

    // residual + bias
    const float4* x4 = (const float4*)(x + (size_t)node * HID + lane * 8);
    const float4* b4 = (const float4*)(bias + lane * 8);
    float4 xa = x4[0], xb = x4[1];
    float4 ba = b4[0], bb = b4[1];
    float va[8];
    va[0] = xa.x + accf[0] * inv + ba.x;
    va[1] = xa.y + accf[1] * inv + ba.y;
    va[2] = xa.z + accf[2] * inv + ba.z;
    va[3] = xa.w + accf[3] * inv + ba.w;
    va[4] = xb.x + accf[4] * inv + bb.x;
    va[5] = xb.y + accf[5] * inv + bb.y;
    va[6] = xb.z + accf[6] * inv + bb.z;
    va[7] = xb.w + accf[7] * inv + bb.w;

    float s = 0.f, q = 0.f;
    #pragma unroll
    for (int k = 0; k < 8; k++) { s += va[k]; q += va[k] * va[k]; }
    #pragma unroll
    for (int o = 16; o > 0; o >>= 1) {
        s += __shfl_xor_sync(0xffffffffu, s, o);
        q += __shfl_xor_sync(0xffffffffu, q, o);
    }
    float mu = s * (1.f / HID);
    float var = q * (1.f / HID) - mu * mu;
    float rstd = rsqrtf(var + 1e-5f);

    const float4* g4 = (const float4*)(gamma + lane * 8);
    const float4* e4 = (const float4*)(beta + lane * 8);
    float4 ga = g4[0], gb = g4[1];
    float4 be = e4[0], bf = e4[1];
    float4 oa, ob;
    oa.x = (va[0] - mu) * rstd * ga.x + be.x;
    oa.y = (va[1] - mu) * rstd * ga.y + be.y;
    oa.z = (va[2] - mu) * rstd * ga.z + be.z;
    oa.w = (va[3] - mu) * rstd * ga.w + be.w;
    ob.x = (va[4] - mu) * rstd * gb.x + bf.x;
    ob.y = (va[5] - mu) * rstd * gb.y + bf.y;
    ob.z = (va[6] - mu) * rstd * gb.z + bf.z;
    ob.w = (va[7] - mu) * rstd * gb.w + bf.w;

    float4* o4 = (float4*)(out + (size_t)node * HID + lane * 8);
    o4[0] = oa;
    o4[1] = ob;
}

// ---------------- launch ----------------
extern "C" void kernel_launch(void* const* d_in, const int* in_sizes, int n_in,
                              void* d_out, int out_size) {
    const float* x        = (const float*)d_in[0];
    const int*   ei       = (const int*)  d_in[1];
    const float* eattr    = (const float*)d_in[2];
    const float* W        = (const float*)d_in[3];
    const float* W_e      = (const float*)d_in[4];
    const float* att_src  = (const float*)d_in[5];
    const float* att_dst  = (const float*)d_in[6];
    const float* att_edge = (const float*)d_in[7];
    const float* bias     = (const float*)d_in[8];
    const float* gamma    = (const float*)d_in[9];
    const float* beta     = (const float*)d_in[10];
    float* out = (float*)d_out;

    cudaFuncSetAttribute(gemm_mma, cudaFuncAttributeMaxDynamicSharedMemorySize, SM_SZ);

    zero_deg<<<(NN + 255) / 256, 256>>>();
    compute_watt<<<1, EDIM * HEADS>>>(W_e, att_edge);
    count_deg<<<(EE + 255) / 256, 256>>>(ei);
    reserve_csr<<<(NN + 255) / 256, 256>>>();

    convert_x<<<(NN * HID / 4 + 255) / 256, 256>>>(x);
    convert_w<<<(HID * HID + 255) / 256, 256>>>(W);

    dim3 ggrid(HID / 64, (NN + 127) / 128);
    gemm_mma<<<ggrid, 256, SM_SZ>>>(att_src, att_dst);

    edge_ea<<<EE / EPB, EPB>>>(ei, eattr);
    aggregate<<<(NN + 7) / 8, 256>>>(x, bias, gamma, beta, out);
}

// round 13
// speedup vs baseline: 1.1304x; 1.0489x over previous
#include <cuda_runtime.h>
#include <cuda_bf16.h>
#include <cstdint>

#define NN 50000
#define EE 800000
#define HID 256
#define HEADS 8
#define CPH 32
#define EDIM 64

// ---------------- scratch ----------------
__device__ __nv_bfloat16  g_xpb [(size_t)NN * HID];  // x @ W (bf16, messages only)
__device__ float          g_ea  [(size_t)EE * HEADS];
__device__ float          g_asrc[(size_t)NN * HEADS];
__device__ float          g_adst[(size_t)NN * HEADS];
__device__ float          g_watt[EDIM * HEADS];
__device__ int            g_deg [NN];
__device__ int            g_start[NN];
__device__ int            g_cur [NN];
__device__ int            g_csr_src[EE];
__device__ int            g_total;
__device__ __nv_bfloat16  g_xhi[(size_t)NN * HID];
__device__ __nv_bfloat16  g_xlo[(size_t)NN * HID];
__device__ __nv_bfloat16  g_whi[HID * HID];   // [n][k] = W[k][n]
__device__ __nv_bfloat16  g_wlo[HID * HID];

// ---------------- zero counters ----------------
__global__ void zero_deg() {
    int i = blockIdx.x * blockDim.x + threadIdx.x;
    if (i < NN) g_deg[i] = 0;
    if (i == 0) g_total = 0;
}

// ---------------- fold W_e with att_edge ----------------
__global__ void compute_watt(const float* __restrict__ W_e,
                             const float* __restrict__ att_edge) {
    int i = threadIdx.x;              // 512 threads
    int d = i >> 3, h = i & 7;
    float s = 0.f;
    #pragma unroll
    for (int c = 0; c < CPH; c++)
        s += W_e[d * (HEADS * CPH) + h * CPH + c] * att_edge[h * CPH + c];
    g_watt[d * HEADS + h] = s;
}

// ---------------- CSR build ----------------
__global__ void count_deg(const int* __restrict__ ei) {
    int e = blockIdx.x * blockDim.x + threadIdx.x;
    if (e < EE) atomicAdd(&g_deg[ei[EE + e]], 1);
}

__global__ void reserve_csr() {
    int n = blockIdx.x * blockDim.x + threadIdx.x;
    int lane = threadIdx.x & 31;
    int d = (n < NN) ? g_deg[n] : 0;
    int incl = d;
    #pragma unroll
    for (int o = 1; o < 32; o <<= 1) {
        int v = __shfl_up_sync(0xffffffffu, incl, o);
        if (lane >= o) incl += v;
    }
    int wtotal = __shfl_sync(0xffffffffu, incl, 31);
    int base = 0;
    if (lane == 31) base = atomicAdd(&g_total, wtotal);
    base = __shfl_sync(0xffffffffu, base, 31);
    int start = base + incl - d;
    if (n < NN) { g_start[n] = start; g_cur[n] = start; }
}

// ---------------- fp32 -> bf16 hi/lo split ----------------
__global__ void convert_x(const float* __restrict__ x) {
    size_t i = ((size_t)blockIdx.x * blockDim.x + threadIdx.x) * 4;
    if (i >= (size_t)NN * HID) return;
    float4 v = *(const float4*)(x + i);
    __nv_bfloat16 h0 = __float2bfloat16(v.x);
    __nv_bfloat16 h1 = __float2bfloat16(v.y);
    __nv_bfloat16 h2 = __float2bfloat16(v.z);
    __nv_bfloat16 h3 = __float2bfloat16(v.w);
    __nv_bfloat162 hi0; hi0.x = h0; hi0.y = h1;
    __nv_bfloat162 hi1; hi1.x = h2; hi1.y = h3;
    __nv_bfloat162 lo0, lo1;
    lo0.x = __float2bfloat16(v.x - __bfloat162float(h0));
    lo0.y = __float2bfloat16(v.y - __bfloat162float(h1));
    lo1.x = __float2bfloat16(v.z - __bfloat162float(h2));
    lo1.y = __float2bfloat16(v.w - __bfloat162float(h3));
    *(__nv_bfloat162*)(g_xhi + i)     = hi0;
    *(__nv_bfloat162*)(g_xhi + i + 2) = hi1;
    *(__nv_bfloat162*)(g_xlo + i)     = lo0;
    *(__nv_bfloat162*)(g_xlo + i + 2) = lo1;
}

__global__ void convert_w(const float* __restrict__ W) {
    int i = blockIdx.x * blockDim.x + threadIdx.x;  // 65536
    if (i >= HID * HID) return;
    int n = i >> 8, k = i & 255;
    float v = W[k * HID + n];                        // transpose: B[n][k] = W[k][n]
    __nv_bfloat16 hi = __float2bfloat16(v);
    g_whi[i] = hi;
    g_wlo[i] = __float2bfloat16(v - __bfloat162float(hi));
}

// ================ mma.sync bf16 GEMM (compute_103-legal tensor path) =======
__device__ __forceinline__ void ldsm_x4(uint32_t addr, uint32_t& r0, uint32_t& r1,
                                        uint32_t& r2, uint32_t& r3) {
    asm volatile("ldmatrix.sync.aligned.m8n8.x4.shared.b16 {%0,%1,%2,%3}, [%4];"
                 : "=r"(r0), "=r"(r1), "=r"(r2), "=r"(r3) : "r"(addr));
}
__device__ __forceinline__ void mma_bf16(float* c, const uint32_t* a,
                                         uint32_t b0, uint32_t b1) {
    asm volatile(
        "mma.sync.aligned.m16n8k16.row.col.f32.bf16.bf16.f32 "
        "{%0,%1,%2,%3}, {%4,%5,%6,%7}, {%8,%9}, {%0,%1,%2,%3};"
        : "+f"(c[0]), "+f"(c[1]), "+f"(c[2]), "+f"(c[3])
        : "r"(a[0]), "r"(a[1]), "r"(a[2]), "r"(a[3]), "r"(b0), "r"(b1));
}
__device__ __forceinline__ uint32_t smem_u32(const void* p) {
    uint32_t a;
    asm("{ .reg .u64 t; cvta.to.shared.u64 t, %1; cvt.u32.u64 %0, t; }"
        : "=r"(a) : "l"(p));
    return a;
}

// SMEM layout (dynamic): swizzled tiles, 128B rows of 8x16B chunks
#define SM_AHI  0
#define SM_ALO  16384
#define SM_BHI  32768
#define SM_BLO  40960
#define SM_ATTS 49152
#define SM_ATTD 49408
#define SM_SZ   49664
#define SWO(row, c) ((uint32_t)((row) * 128 + (((c) ^ ((row) & 7)) << 4)))

__global__ __launch_bounds__(256, 2) void gemm_mma(const float* __restrict__ att_src,
                                                   const float* __restrict__ att_dst) {
    extern __shared__ char smem[];
    uint32_t sb = smem_u32(smem);
    int tid = threadIdx.x;
    int wid = tid >> 5;
    int lane = tid & 31;
    int bm = blockIdx.y * 128;
    int bn = blockIdx.x * 64;
    int mrow0 = (wid & 3) * 32;
    int ncol0 = (wid >> 2) * 32;

    float* satts = (float*)(smem + SM_ATTS);
    float* sattd = (float*)(smem + SM_ATTD);
    if (tid < 64) {
        satts[tid] = att_src[bn + tid];
        sattd[tid] = att_dst[bn + tid];
    }

    float acc[2][4][4];
    #pragma unroll
    for (int ma = 0; ma < 2; ma++)
        #pragma unroll
        for (int nb = 0; nb < 4; nb++)
            #pragma unroll
            for (int j = 0; j < 4; j++) acc[ma][nb][j] = 0.f;

    #pragma unroll 1
    for (int kc = 0; kc < 4; kc++) {
        // ---- stage A (128x64, hi+lo) ----
        #pragma unroll
        for (int j = 0; j < 4; j++) {
            int i = tid + j * 256;
            int row = i >> 3, c = i & 7;
            uint32_t off = SWO(row, c);
            int rg = bm + row;
            uint4 vh = make_uint4(0, 0, 0, 0), vl = make_uint4(0, 0, 0, 0);
            if (rg < NN) {
                const __nv_bfloat16* ph = g_xhi + ((size_t)rg << 8) + kc * 64 + c * 8;
                const __nv_bfloat16* pl = g_xlo + ((size_t)rg << 8) + kc * 64 + c * 8;
                vh = *(const uint4*)ph;
                vl = *(const uint4*)pl;
            }
            *(uint4*)(smem + SM_AHI + off) = vh;
            *(uint4*)(smem + SM_ALO + off) = vl;
        }
        // ---- stage B (64x64, hi+lo), rows are n, cols are k ----
        #pragma unroll
        for (int j = 0; j < 2; j++) {
            int i = tid + j * 256;
            int n = i >> 3, c = i & 7;
            uint32_t off = SWO(n, c);
            const __nv_bfloat16* ph = g_whi + ((size_t)(bn + n) << 8) + kc * 64 + c * 8;
            const __nv_bfloat16* pl = g_wlo + ((size_t)(bn + n) << 8) + kc * 64 + c * 8;
            *(uint4*)(smem + SM_BHI + off) = *(const uint4*)ph;
            *(uint4*)(smem + SM_BLO + off) = *(const uint4*)pl;
        }
        __syncthreads();

        #pragma unroll
        for (int ks = 0; ks < 4; ks++) {
            uint32_t ahi[2][4], alo[2][4];
            #pragma unroll
            for (int ma = 0; ma < 2; ma++) {
                int row = mrow0 + ma * 16 + (lane & 15);
                int c = ks * 2 + (lane >> 4);
                uint32_t off = SWO(row, c);
                ldsm_x4(sb + SM_AHI + off, ahi[ma][0], ahi[ma][1], ahi[ma][2], ahi[ma][3]);
                ldsm_x4(sb + SM_ALO + off, alo[ma][0], alo[ma][1], alo[ma][2], alo[ma][3]);
            }
            uint32_t bhi[4][2], blo[4][2];
            #pragma unroll
            for (int nb2 = 0; nb2 < 2; nb2++) {
                int n = ncol0 + nb2 * 16 + (lane & 7) + ((lane & 16) >> 1);
                int c = ks * 2 + ((lane >> 3) & 1);
                uint32_t off = SWO(n, c);
                ldsm_x4(sb + SM_BHI + off, bhi[nb2 * 2][0], bhi[nb2 * 2][1],
                        bhi[nb2 * 2 + 1][0], bhi[nb2 * 2 + 1][1]);
                ldsm_x4(sb + SM_BLO + off, blo[nb2 * 2][0], blo[nb2 * 2][1],
                        blo[nb2 * 2 + 1][0], blo[nb2 * 2 + 1][1]);
            }
            #pragma unroll
            for (int ma = 0; ma < 2; ma++)
                #pragma unroll
                for (int nb = 0; nb < 4; nb++) {
                    mma_bf16(acc[ma][nb], ahi[ma], bhi[nb][0], bhi[nb][1]);
                    mma_bf16(acc[ma][nb], ahi[ma], blo[nb][0], blo[nb][1]);
                    mma_bf16(acc[ma][nb], alo[ma], bhi[nb][0], bhi[nb][1]);
                }
        }
        __syncthreads();
    }

    // ---- epilogue: store xp (bf16) + fused a_src/a_dst (one head per warp) ----
    int head = (bn + ncol0) >> 5;
    #pragma unroll
    for (int ma = 0; ma < 2; ma++) {
        int row0 = bm + mrow0 + ma * 16 + (lane >> 2);
        int row1 = row0 + 8;
        float ps0 = 0.f, pd0 = 0.f, ps1 = 0.f, pd1 = 0.f;
        #pragma unroll
        for (int nb = 0; nb < 4; nb++) {
            int colt = ncol0 + nb * 8 + (lane & 3) * 2;   // col within 64-tile
            float c0 = acc[ma][nb][0], c1 = acc[ma][nb][1];
            float c2 = acc[ma][nb][2], c3 = acc[ma][nb][3];
            if (row0 < NN) {
                __nv_bfloat162 p; p.x = __float2bfloat16(c0); p.y = __float2bfloat16(c1);
                *(__nv_bfloat162*)(g_xpb + (size_t)row0 * HID + bn + colt) = p;
            }
            if (row1 < NN) {
                __nv_bfloat162 p; p.x = __float2bfloat16(c2); p.y = __float2bfloat16(c3);
                *(__nv_bfloat162*)(g_xpb + (size_t)row1 * HID + bn + colt) = p;
            }
            float as0 = satts[colt], as1 = satts[colt + 1];
            float ad0 = sattd[colt], ad1 = sattd[colt + 1];
            ps0 += c0 * as0 + c1 * as1;
            pd0 += c0 * ad0 + c1 * ad1;
            ps1 += c2 * as0 + c3 * as1;
            pd1 += c2 * ad0 + c3 * ad1;
        }
        #pragma unroll
        for (int o = 1; o <= 2; o <<= 1) {
            ps0 += __shfl_xor_sync(0xffffffffu, ps0, o);
            pd0 += __shfl_xor_sync(0xffffffffu, pd0, o);
            ps1 += __shfl_xor_sync(0xffffffffu, ps1, o);
            pd1 += __shfl_xor_sync(0xffffffffu, pd1, o);
        }
        if ((lane & 3) == 0) {
            if (row0 < NN) {
                g_asrc[(size_t)row0 * HEADS + head] = ps0;
                g_adst[(size_t)row0 * HEADS + head] = pd0;
            }
            if (row1 < NN) {
                g_asrc[(size_t)row1 * HEADS + head] = ps1;
                g_adst[(size_t)row1 * HEADS + head] = pd1;
            }
        }
    }
}

// -------- edge pass: smem-staged eattr (coalesced), leakyrelu+exp, scatter --
#define EPB 128   // edges per block (EE % EPB == 0)
__global__ __launch_bounds__(EPB) void edge_ea(const int* __restrict__ ei,
                                               const float* __restrict__ eattr) {
    __shared__ float4 ws4[EDIM * 2];       // [d*2] = heads0-3, [d*2+1] = heads4-7
    __shared__ float4 tile[EPB * 17];      // 16 data f4 + 1 pad per edge row
    int tid = threadIdx.x;
    for (int i = tid; i < EDIM * 2; i += EPB)
        ws4[i] = ((const float4*)g_watt)[i];

    int e0 = blockIdx.x * EPB;
    // stage eattr: EPB edges * 16 float4, fully coalesced global reads
    const float4* gsrc = (const float4*)(eattr + (size_t)e0 * EDIM);
    #pragma unroll
    for (int j = 0; j < 16; j++) {
        int idx = tid + j * EPB;           // 0 .. EPB*16-1
        int er = idx >> 4, c = idx & 15;
        tile[er * 17 + c] = gsrc[idx];
    }
    __syncthreads();

    int e = e0 + tid;
    int src = ei[e];
    int dst = ei[EE + e];

    const float4* as4 = (const float4*)(g_asrc + (size_t)src * HEADS);
    const float4* ad4 = (const float4*)(g_adst + (size_t)dst * HEADS);
    float4 as0 = as4[0], as1 = as4[1];
    float4 ad0 = ad4[0], ad1 = ad4[1];

    float4 accA = make_float4(0.f, 0.f, 0.f, 0.f);
    float4 accB = make_float4(0.f, 0.f, 0.f, 0.f);

    const float4* row = tile + tid * 17;   // conflict-free per 8-lane phase
    #pragma unroll
    for (int d4 = 0; d4 < EDIM / 4; d4++) {
        float4 v = row[d4];
        int d = d4 * 4;
        float4 w;
        w = ws4[(d + 0) * 2];     accA.x += v.x * w.x; accA.y += v.x * w.y; accA.z += v.x * w.z; accA.w += v.x * w.w;
        w = ws4[(d + 0) * 2 + 1]; accB.x += v.x * w.x; accB.y += v.x * w.y; accB.z += v.x * w.z; accB.w += v.x * w.w;
        w = ws4[(d + 1) * 2];     accA.x += v.y * w.x; accA.y += v.y * w.y; accA.z += v.y * w.z; accA.w += v.y * w.w;
        w = ws4[(d + 1) * 2 + 1]; accB.x += v.y * w.x; accB.y += v.y * w.y; accB.z += v.y * w.z; accB.w += v.y * w.w;
        w = ws4[(d + 2) * 2];     accA.x += v.z * w.x; accA.y += v.z * w.y; accA.z += v.z * w.z; accA.w += v.z * w.w;
        w = ws4[(d + 2) * 2 + 1]; accB.x += v.z * w.x; accB.y += v.z * w.y; accB.z += v.z * w.z; accB.w += v.z * w.w;
        w = ws4[(d + 3) * 2];     accA.x += v.w * w.x; accA.y += v.w * w.y; accA.z += v.w * w.z; accA.w += v.w * w.w;
        w = ws4[(d + 3) * 2 + 1]; accB.x += v.w * w.x; accB.y += v.w * w.y; accB.z += v.w * w.z; accB.w += v.w * w.w;
    }

    float a[HEADS];
    a[0] = as0.x + ad0.x + accA.x;
    a[1] = as0.y + ad0.y + accA.y;
    a[2] = as0.z + ad0.z + accA.z;
    a[3] = as0.w + ad0.w + accA.w;
    a[4] = as1.x + ad1.x + accB.x;
    a[5] = as1.y + ad1.y + accB.y;
    a[6] = as1.z + ad1.z + accB.z;
    a[7] = as1.w + ad1.w + accB.w;

    #pragma unroll
    for (int h = 0; h < HEADS; h++) {
        float al = a[h];
        al = (al > 0.f) ? al : 0.2f * al;   // LeakyReLU
        a[h] = __expf(al);                  // softmax is shift-invariant
    }
    int pos = atomicAdd(&g_cur[dst], 1);    // fused CSR slot reservation
    g_csr_src[pos] = src;
    float4* out = (float4*)(g_ea + (size_t)pos * HEADS);
    out[0] = make_float4(a[0], a[1], a[2], a[3]);
    out[1] = make_float4(a[4], a[5], a[6], a[7]);
}

// -------- aggregate: 1 warp/node, batched index loads, bf16 gather, LN ------
__global__ __launch_bounds__(256) void aggregate(const float* __restrict__ x,
                                                 const float* __restrict__ bias,
                                                 const float* __restrict__ gamma,
                                                 const float* __restrict__ beta,
                                                 float* __restrict__ out) {
    int node = blockIdx.x * 8 + (threadIdx.x >> 5);
    int lane = threadIdx.x & 31;
    if (node >= NN) return;
    int start = g_start[node];
    int deg   = g_deg[node];
    int myhead = lane >> 2;          // channels lane*8 .. lane*8+7 are all in this head
    int epair = myhead >> 1;         // ea float2 pair index for my head

    float accf[8];
    #pragma unroll
    for (int k = 0; k < 8; k++) accf[k] = 0.f;
    float2 den2 = make_float2(0.f, 0.f);   // heads (lane&3)*2, +1

    int i0 = 0;
    for (; i0 + 8 <= deg; i0 += 8) {
        int p0 = start + i0;
        int srcs = (lane < 8) ? g_csr_src[p0 + lane] : 0;
        float2 eav = *(const float2*)(g_ea + (size_t)(p0 + (lane >> 2)) * HEADS + (lane & 3) * 2);
        den2.x += eav.x;
        den2.y += eav.y;
        #pragma unroll
        for (int j = 0; j < 8; j++) {
            int src = __shfl_sync(0xffffffffu, srcs, j);
            float ex = __shfl_sync(0xffffffffu, eav.x, j * 4 + epair);
            float ey = __shfl_sync(0xffffffffu, eav.y, j * 4 + epair);
            float eh = (myhead & 1) ? ey : ex;
            uint4 v = *(const uint4*)(g_xpb + (size_t)src * HID + lane * 8);
            float2 f0 = __bfloat1622float2(*(__nv_bfloat162*)&v.x);
            float2 f1 = __bfloat1622float2(*(__nv_bfloat162*)&v.y);
            float2 f2 = __bfloat1622float2(*(__nv_bfloat162*)&v.z);
            float2 f3 = __bfloat1622float2(*(__nv_bfloat162*)&v.w);
            accf[0] += eh * f0.x; accf[1] += eh * f0.y;
            accf[2] += eh * f1.x; accf[3] += eh * f1.y;
            accf[4] += eh * f2.x; accf[5] += eh * f2.y;
            accf[6] += eh * f3.x; accf[7] += eh * f3.y;
        }
    }
    if (i0 < deg) {
        int rem = deg - i0;
        int p0 = start + i0;
        int srcs = (lane < rem && lane < 8) ? g_csr_src[p0 + lane] : 0;
        float2 eav = make_float2(0.f, 0.f);
        if ((lane >> 2) < rem)
            eav = *(const float2*)(g_ea + (size_t)(p0 + (lane >> 2)) * HEADS + (lane & 3) * 2);
        den2.x += eav.x;
        den2.y += eav.y;
        for (int j = 0; j < rem; j++) {
            int src = __shfl_sync(0xffffffffu, srcs, j);
            float ex = __shfl_sync(0xffffffffu, eav.x, j * 4 + epair);
            float ey = __shfl_sync(0xffffffffu, eav.y, j * 4 + epair);
            float eh = (myhead & 1) ? ey : ex;
            uint4 v = *(const uint4*)(g_xpb + (size_t)src * HID + lane * 8);
            float2 f0 = __bfloat1622float2(*(__nv_bfloat162*)&v.x);
            float2 f1 = __bfloat1622float2(*(__nv_bfloat162*)&v.y);
            float2 f2 = __bfloat1622float2(*(__nv_bfloat162*)&v.z);
            float2 f3 = __bfloat1622float2(*(__nv_bfloat162*)&v.w);
            accf[0] += eh * f0.x; accf[1] += eh * f0.y;
            accf[2] += eh * f1.x; accf[3] += eh * f1.y;
            accf[4] += eh * f2.x; accf[5] += eh * f2.y;
            accf[6] += eh * f3.x; accf[7] += eh * f3.y;
        }
    }

    // den: reduce over edge-slot lane bits (2,3,4); lanes grouped by (lane&3)
    #pragma unroll
    for (int o = 4; o < 32; o <<= 1) {
        den2.x += __shfl_xor_sync(0xffffffffu, den2.x, o);
        den2.y += __shfl_xor_sync(0xffffffffu, den2.y, o);
    }
    float dx = __shfl_sync(0xffffffffu, den2.x, epair);  // head myhead&~1
    float dy = __shfl_sync(0xffffffffu, den2.y, epair);  // head myhead|1
    float den = (myhead & 1) ? dy : dx;
    float inv = 1.f / (den + 1e-16f);

    // residual + bias
    const float4* x4 = (const float4*)(x + (size_t)node * HID + lane * 8);
    const float4* b4 = (const float4*)(bias + lane * 8);
    float4 xa = x4[0], xb = x4[1];
    float4 ba = b4[0], bb = b4[1];
    float va[8];
    va[0] = xa.x + accf[0] * inv + ba.x;
    va[1] = xa.y + accf[1] * inv + ba.y;
    va[2] = xa.z + accf[2] * inv + ba.z;
    va[3] = xa.w + accf[3] * inv + ba.w;
    va[4] = xb.x + accf[4] * inv + bb.x;
    va[5] = xb.y + accf[5] * inv + bb.y;
    va[6] = xb.z + accf[6] * inv + bb.z;
    va[7] = xb.w + accf[7] * inv + bb.w;

    float s = 0.f, q = 0.f;
    #pragma unroll
    for (int k = 0; k < 8; k++) { s += va[k]; q += va[k] * va[k]; }
    #pragma unroll
    for (int o = 16; o > 0; o >>= 1) {
        s += __shfl_xor_sync(0xffffffffu, s, o);
        q += __shfl_xor_sync(0xffffffffu, q, o);
    }
    float mu = s * (1.f / HID);
    float var = q * (1.f / HID) - mu * mu;
    float rstd = rsqrtf(var + 1e-5f);

    const float4* g4 = (const float4*)(gamma + lane * 8);
    const float4* e4 = (const float4*)(beta + lane * 8);
    float4 ga = g4[0], gb = g4[1];
    float4 be = e4[0], bf = e4[1];
    float4 oa, ob;
    oa.x = (va[0] - mu) * rstd * ga.x + be.x;
    oa.y = (va[1] - mu) * rstd * ga.y + be.y;
    oa.z = (va[2] - mu) * rstd * ga.z + be.z;
    oa.w = (va[3] - mu) * rstd * ga.w + be.w;
    ob.x = (va[4] - mu) * rstd * gb.x + bf.x;
    ob.y = (va[5] - mu) * rstd * gb.y + bf.y;
    ob.z = (va[6] - mu) * rstd * gb.z + bf.z;
    ob.w = (va[7] - mu) * rstd * gb.w + bf.w;

    float4* o4 = (float4*)(out + (size_t)node * HID + lane * 8);
    o4[0] = oa;
    o4[1] = ob;
}

// ---------------- launch: fork CSR chain onto a side stream ----------------
extern "C" void kernel_launch(void* const* d_in, const int* in_sizes, int n_in,
                              void* d_out, int out_size) {
    const float* x        = (const float*)d_in[0];
    const int*   ei       = (const int*)  d_in[1];
    const float* eattr    = (const float*)d_in[2];
    const float* W        = (const float*)d_in[3];
    const float* W_e      = (const float*)d_in[4];
    const float* att_src  = (const float*)d_in[5];
    const float* att_dst  = (const float*)d_in[6];
    const float* att_edge = (const float*)d_in[7];
    const float* bias     = (const float*)d_in[8];
    const float* gamma    = (const float*)d_in[9];
    const float* beta     = (const float*)d_in[10];
    float* out = (float*)d_out;

    cudaFuncSetAttribute(gemm_mma, cudaFuncAttributeMaxDynamicSharedMemorySize, SM_SZ);

    // Fresh handles each call (never destroyed: destroying mid-capture would
    // invalidate the graph; a few host-side handles per host invocation only).
    cudaStream_t side;
    cudaStreamCreateWithFlags(&side, cudaStreamNonBlocking);
    cudaEvent_t evFork, evJoin;
    cudaEventCreateWithFlags(&evFork, cudaEventDisableTiming);
    cudaEventCreateWithFlags(&evJoin, cudaEventDisableTiming);

    // fork
    cudaEventRecord(evFork, 0);
    cudaStreamWaitEvent(side, evFork, 0);

    // side branch: CSR build + watt fold (independent of converts/GEMM)
    zero_deg<<<(NN + 255) / 256, 256, 0, side>>>();
    compute_watt<<<1, EDIM * HEADS, 0, side>>>(W_e, att_edge);
    count_deg<<<(EE + 255) / 256, 256, 0, side>>>(ei);
    reserve_csr<<<(NN + 255) / 256, 256, 0, side>>>();

    // main branch: converts + tensor GEMM (+ fused node_att)
    convert_x<<<(NN * HID / 4 + 255) / 256, 256>>>(x);
    convert_w<<<(HID * HID + 255) / 256, 256>>>(W);
    dim3 ggrid(HID / 64, (NN + 127) / 128);
    gemm_mma<<<ggrid, 256, SM_SZ>>>(att_src, att_dst);

    // join: edge_ea needs both branches
    cudaEventRecord(evJoin, side);
    cudaStreamWaitEvent(0, evJoin, 0);

    edge_ea<<<EE / EPB, EPB>>>(ei, eattr);
    aggregate<<<(NN + 7) / 8, 256>>>(x, bias, gamma, beta, out);
}

// round 14
// speedup vs baseline: 1.1962x; 1.0583x over previous
#include <cuda_runtime.h>
#include <cuda_bf16.h>
#include <cstdint>

#define NN 50000
#define EE 800000
#define HID 256
#define HEADS 8
#define CPH 32
#define EDIM 64

// ---------------- scratch ----------------
__device__ __nv_bfloat16  g_xpb [(size_t)NN * HID];  // x @ W (bf16, messages only)
__device__ float          g_ea  [(size_t)EE * HEADS];
__device__ float          g_aedge[(size_t)EE * HEADS]; // eattr @ w_att
__device__ float          g_asrc[(size_t)NN * HEADS];
__device__ float          g_adst[(size_t)NN * HEADS];
__device__ float          g_watt[EDIM * HEADS];
__device__ int            g_deg [NN];
__device__ int            g_start[NN];
__device__ int            g_cur [NN];
__device__ int            g_csr_src[EE];
__device__ int            g_total;
__device__ __nv_bfloat16  g_xhi[(size_t)NN * HID];
__device__ __nv_bfloat16  g_xlo[(size_t)NN * HID];
__device__ __nv_bfloat16  g_whi[HID * HID];   // [n][k] = W[k][n]
__device__ __nv_bfloat16  g_wlo[HID * HID];

// ---------------- zero counters ----------------
__global__ void zero_deg() {
    int i = blockIdx.x * blockDim.x + threadIdx.x;
    if (i < NN) g_deg[i] = 0;
    if (i == 0) g_total = 0;
}

// ---------------- fold W_e with att_edge ----------------
__global__ void compute_watt(const float* __restrict__ W_e,
                             const float* __restrict__ att_edge) {
    int i = threadIdx.x;              // 512 threads
    int d = i >> 3, h = i & 7;
    float s = 0.f;
    #pragma unroll
    for (int c = 0; c < CPH; c++)
        s += W_e[d * (HEADS * CPH) + h * CPH + c] * att_edge[h * CPH + c];
    g_watt[d * HEADS + h] = s;
}

// ---------------- CSR build ----------------
__global__ void count_deg(const int* __restrict__ ei) {
    int e = blockIdx.x * blockDim.x + threadIdx.x;
    if (e < EE) atomicAdd(&g_deg[ei[EE + e]], 1);
}

__global__ void reserve_csr() {
    int n = blockIdx.x * blockDim.x + threadIdx.x;
    int lane = threadIdx.x & 31;
    int d = (n < NN) ? g_deg[n] : 0;
    int incl = d;
    #pragma unroll
    for (int o = 1; o < 32; o <<= 1) {
        int v = __shfl_up_sync(0xffffffffu, incl, o);
        if (lane >= o) incl += v;
    }
    int wtotal = __shfl_sync(0xffffffffu, incl, 31);
    int base = 0;
    if (lane == 31) base = atomicAdd(&g_total, wtotal);
    base = __shfl_sync(0xffffffffu, base, 31);
    int start = base + incl - d;
    if (n < NN) { g_start[n] = start; g_cur[n] = start; }
}

// ---------------- fp32 -> bf16 hi/lo split ----------------
__global__ void convert_x(const float* __restrict__ x) {
    size_t i = ((size_t)blockIdx.x * blockDim.x + threadIdx.x) * 4;
    if (i >= (size_t)NN * HID) return;
    float4 v = *(const float4*)(x + i);
    __nv_bfloat16 h0 = __float2bfloat16(v.x);
    __nv_bfloat16 h1 = __float2bfloat16(v.y);
    __nv_bfloat16 h2 = __float2bfloat16(v.z);
    __nv_bfloat16 h3 = __float2bfloat16(v.w);
    __nv_bfloat162 hi0; hi0.x = h0; hi0.y = h1;
    __nv_bfloat162 hi1; hi1.x = h2; hi1.y = h3;
    __nv_bfloat162 lo0, lo1;
    lo0.x = __float2bfloat16(v.x - __bfloat162float(h0));
    lo0.y = __float2bfloat16(v.y - __bfloat162float(h1));
    lo1.x = __float2bfloat16(v.z - __bfloat162float(h2));
    lo1.y = __float2bfloat16(v.w - __bfloat162float(h3));
    *(__nv_bfloat162*)(g_xhi + i)     = hi0;
    *(__nv_bfloat162*)(g_xhi + i + 2) = hi1;
    *(__nv_bfloat162*)(g_xlo + i)     = lo0;
    *(__nv_bfloat162*)(g_xlo + i + 2) = lo1;
}

__global__ void convert_w(const float* __restrict__ W) {
    int i = blockIdx.x * blockDim.x + threadIdx.x;  // 65536
    if (i >= HID * HID) return;
    int n = i >> 8, k = i & 255;
    float v = W[k * HID + n];                        // transpose: B[n][k] = W[k][n]
    __nv_bfloat16 hi = __float2bfloat16(v);
    g_whi[i] = hi;
    g_wlo[i] = __float2bfloat16(v - __bfloat162float(hi));
}

// ================ mma.sync bf16 GEMM (compute_103-legal tensor path) =======
__device__ __forceinline__ void ldsm_x4(uint32_t addr, uint32_t& r0, uint32_t& r1,
                                        uint32_t& r2, uint32_t& r3) {
    asm volatile("ldmatrix.sync.aligned.m8n8.x4.shared.b16 {%0,%1,%2,%3}, [%4];"
                 : "=r"(r0), "=r"(r1), "=r"(r2), "=r"(r3) : "r"(addr));
}
__device__ __forceinline__ void mma_bf16(float* c, const uint32_t* a,
                                         uint32_t b0, uint32_t b1) {
    asm volatile(
        "mma.sync.aligned.m16n8k16.row.col.f32.bf16.bf16.f32 "
        "{%0,%1,%2,%3}, {%4,%5,%6,%7}, {%8,%9}, {%0,%1,%2,%3};"
        : "+f"(c[0]), "+f"(c[1]), "+f"(c[2]), "+f"(c[3])
        : "r"(a[0]), "r"(a[1]), "r"(a[2]), "r"(a[3]), "r"(b0), "r"(b1));
}
__device__ __forceinline__ uint32_t smem_u32(const void* p) {
    uint32_t a;
    asm("{ .reg .u64 t; cvta.to.shared.u64 t, %1; cvt.u32.u64 %0, t; }"
        : "=r"(a) : "l"(p));
    return a;
}

// SMEM layout (dynamic): swizzled tiles, 128B rows of 8x16B chunks
#define SM_AHI  0
#define SM_ALO  16384
#define SM_BHI  32768
#define SM_BLO  40960
#define SM_ATTS 49152
#define SM_ATTD 49408
#define SM_SZ   49664
#define SWO(row, c) ((uint32_t)((row) * 128 + (((c) ^ ((row) & 7)) << 4)))

__global__ __launch_bounds__(256, 2) void gemm_mma(const float* __restrict__ att_src,
                                                   const float* __restrict__ att_dst) {
    extern __shared__ char smem[];
    uint32_t sb = smem_u32(smem);
    int tid = threadIdx.x;
    int wid = tid >> 5;
    int lane = tid & 31;
    int bm = blockIdx.y * 128;
    int bn = blockIdx.x * 64;
    int mrow0 = (wid & 3) * 32;
    int ncol0 = (wid >> 2) * 32;

    float* satts = (float*)(smem + SM_ATTS);
    float* sattd = (float*)(smem + SM_ATTD);
    if (tid < 64) {
        satts[tid] = att_src[bn + tid];
        sattd[tid] = att_dst[bn + tid];
    }

    float acc[2][4][4];
    #pragma unroll
    for (int ma = 0; ma < 2; ma++)
        #pragma unroll
        for (int nb = 0; nb < 4; nb++)
            #pragma unroll
            for (int j = 0; j < 4; j++) acc[ma][nb][j] = 0.f;

    #pragma unroll 1
    for (int kc = 0; kc < 4; kc++) {
        // ---- stage A (128x64, hi+lo) ----
        #pragma unroll
        for (int j = 0; j < 4; j++) {
            int i = tid + j * 256;
            int row = i >> 3, c = i & 7;
            uint32_t off = SWO(row, c);
            int rg = bm + row;
            uint4 vh = make_uint4(0, 0, 0, 0), vl = make_uint4(0, 0, 0, 0);
            if (rg < NN) {
                const __nv_bfloat16* ph = g_xhi + ((size_t)rg << 8) + kc * 64 + c * 8;
                const __nv_bfloat16* pl = g_xlo + ((size_t)rg << 8) + kc * 64 + c * 8;
                vh = *(const uint4*)ph;
                vl = *(const uint4*)pl;
            }
            *(uint4*)(smem + SM_AHI + off) = vh;
            *(uint4*)(smem + SM_ALO + off) = vl;
        }
        // ---- stage B (64x64, hi+lo), rows are n, cols are k ----
        #pragma unroll
        for (int j = 0; j < 2; j++) {
            int i = tid + j * 256;
            int n = i >> 3, c = i & 7;
            uint32_t off = SWO(n, c);
            const __nv_bfloat16* ph = g_whi + ((size_t)(bn + n) << 8) + kc * 64 + c * 8;
            const __nv_bfloat16* pl = g_wlo + ((size_t)(bn + n) << 8) + kc * 64 + c * 8;
            *(uint4*)(smem + SM_BHI + off) = *(const uint4*)ph;
            *(uint4*)(smem + SM_BLO + off) = *(const uint4*)pl;
        }
        __syncthreads();

        #pragma unroll
        for (int ks = 0; ks < 4; ks++) {
            uint32_t ahi[2][4], alo[2][4];
            #pragma unroll
            for (int ma = 0; ma < 2; ma++) {
                int row = mrow0 + ma * 16 + (lane & 15);
                int c = ks * 2 + (lane >> 4);
                uint32_t off = SWO(row, c);
                ldsm_x4(sb + SM_AHI + off, ahi[ma][0], ahi[ma][1], ahi[ma][2], ahi[ma][3]);
                ldsm_x4(sb + SM_ALO + off, alo[ma][0], alo[ma][1], alo[ma][2], alo[ma][3]);
            }
            uint32_t bhi[4][2], blo[4][2];
            #pragma unroll
            for (int nb2 = 0; nb2 < 2; nb2++) {
                int n = ncol0 + nb2 * 16 + (lane & 7) + ((lane & 16) >> 1);
                int c = ks * 2 + ((lane >> 3) & 1);
                uint32_t off = SWO(n, c);
                ldsm_x4(sb + SM_BHI + off, bhi[nb2 * 2][0], bhi[nb2 * 2][1],
                        bhi[nb2 * 2 + 1][0], bhi[nb2 * 2 + 1][1]);
                ldsm_x4(sb + SM_BLO + off, blo[nb2 * 2][0], blo[nb2 * 2][1],
                        blo[nb2 * 2 + 1][0], blo[nb2 * 2 + 1][1]);
            }
            #pragma unroll
            for (int ma = 0; ma < 2; ma++)
                #pragma unroll
                for (int nb = 0; nb < 4; nb++) {
                    mma_bf16(acc[ma][nb], ahi[ma], bhi[nb][0], bhi[nb][1]);
                    mma_bf16(acc[ma][nb], ahi[ma], blo[nb][0], blo[nb][1]);
                    mma_bf16(acc[ma][nb], alo[ma], bhi[nb][0], bhi[nb][1]);
                }
        }
        __syncthreads();
    }

    // ---- epilogue: store xp (bf16) + fused a_src/a_dst (one head per warp) ----
    int head = (bn + ncol0) >> 5;
    #pragma unroll
    for (int ma = 0; ma < 2; ma++) {
        int row0 = bm + mrow0 + ma * 16 + (lane >> 2);
        int row1 = row0 + 8;
        float ps0 = 0.f, pd0 = 0.f, ps1 = 0.f, pd1 = 0.f;
        #pragma unroll
        for (int nb = 0; nb < 4; nb++) {
            int colt = ncol0 + nb * 8 + (lane & 3) * 2;   // col within 64-tile
            float c0 = acc[ma][nb][0], c1 = acc[ma][nb][1];
            float c2 = acc[ma][nb][2], c3 = acc[ma][nb][3];
            if (row0 < NN) {
                __nv_bfloat162 p; p.x = __float2bfloat16(c0); p.y = __float2bfloat16(c1);
                *(__nv_bfloat162*)(g_xpb + (size_t)row0 * HID + bn + colt) = p;
            }
            if (row1 < NN) {
                __nv_bfloat162 p; p.x = __float2bfloat16(c2); p.y = __float2bfloat16(c3);
                *(__nv_bfloat162*)(g_xpb + (size_t)row1 * HID + bn + colt) = p;
            }
            float as0 = satts[colt], as1 = satts[colt + 1];
            float ad0 = sattd[colt], ad1 = sattd[colt + 1];
            ps0 += c0 * as0 + c1 * as1;
            pd0 += c0 * ad0 + c1 * ad1;
            ps1 += c2 * as0 + c3 * as1;
            pd1 += c2 * ad0 + c3 * ad1;
        }
        #pragma unroll
        for (int o = 1; o <= 2; o <<= 1) {
            ps0 += __shfl_xor_sync(0xffffffffu, ps0, o);
            pd0 += __shfl_xor_sync(0xffffffffu, pd0, o);
            ps1 += __shfl_xor_sync(0xffffffffu, ps1, o);
            pd1 += __shfl_xor_sync(0xffffffffu, pd1, o);
        }
        if ((lane & 3) == 0) {
            if (row0 < NN) {
                g_asrc[(size_t)row0 * HEADS + head] = ps0;
                g_adst[(size_t)row0 * HEADS + head] = pd0;
            }
            if (row1 < NN) {
                g_asrc[(size_t)row1 * HEADS + head] = ps1;
                g_adst[(size_t)row1 * HEADS + head] = pd1;
            }
        }
    }
}

// -------- edge pass A (side stream): a_edge = eattr @ w_att ----------------
#define EPB 128   // edges per block (EE % EPB == 0)
__global__ __launch_bounds__(EPB) void edge_aedge(const float* __restrict__ eattr) {
    __shared__ float4 ws4[EDIM * 2];       // [d*2] = heads0-3, [d*2+1] = heads4-7
    __shared__ float4 tile[EPB * 17];      // 16 data f4 + 1 pad per edge row
    int tid = threadIdx.x;
    for (int i = tid; i < EDIM * 2; i += EPB)
        ws4[i] = ((const float4*)g_watt)[i];

    int e0 = blockIdx.x * EPB;
    const float4* gsrc = (const float4*)(eattr + (size_t)e0 * EDIM);
    #pragma unroll
    for (int j = 0; j < 16; j++) {
        int idx = tid + j * EPB;           // 0 .. EPB*16-1
        int er = idx >> 4, c = idx & 15;
        tile[er * 17 + c] = gsrc[idx];
    }
    __syncthreads();

    float4 accA = make_float4(0.f, 0.f, 0.f, 0.f);
    float4 accB = make_float4(0.f, 0.f, 0.f, 0.f);

    const float4* row = tile + tid * 17;   // conflict-free per 8-lane phase
    #pragma unroll
    for (int d4 = 0; d4 < EDIM / 4; d4++) {
        float4 v = row[d4];
        int d = d4 * 4;
        float4 w;
        w = ws4[(d + 0) * 2];     accA.x += v.x * w.x; accA.y += v.x * w.y; accA.z += v.x * w.z; accA.w += v.x * w.w;
        w = ws4[(d + 0) * 2 + 1]; accB.x += v.x * w.x; accB.y += v.x * w.y; accB.z += v.x * w.z; accB.w += v.x * w.w;
        w = ws4[(d + 1) * 2];     accA.x += v.y * w.x; accA.y += v.y * w.y; accA.z += v.y * w.z; accA.w += v.y * w.w;
        w = ws4[(d + 1) * 2 + 1]; accB.x += v.y * w.x; accB.y += v.y * w.y; accB.z += v.y * w.z; accB.w += v.y * w.w;
        w = ws4[(d + 2) * 2];     accA.x += v.z * w.x; accA.y += v.z * w.y; accA.z += v.z * w.z; accA.w += v.z * w.w;
        w = ws4[(d + 2) * 2 + 1]; accB.x += v.z * w.x; accB.y += v.z * w.y; accB.z += v.z * w.z; accB.w += v.z * w.w;
        w = ws4[(d + 3) * 2];     accA.x += v.w * w.x; accA.y += v.w * w.y; accA.z += v.w * w.z; accA.w += v.w * w.w;
        w = ws4[(d + 3) * 2 + 1]; accB.x += v.w * w.x; accB.y += v.w * w.y; accB.z += v.w * w.z; accB.w += v.w * w.w;
    }

    float4* outp = (float4*)(g_aedge + (size_t)(e0 + tid) * HEADS);
    outp[0] = accA;
    outp[1] = accB;
}

// -------- edge pass B (after join): gather + leakyrelu + exp + scatter ------
__global__ __launch_bounds__(256) void edge_scatter(const int* __restrict__ ei) {
    int e = blockIdx.x * blockDim.x + threadIdx.x;
    if (e >= EE) return;
    int src = ei[e];
    int dst = ei[EE + e];

    const float4* ae4 = (const float4*)(g_aedge + (size_t)e * HEADS);
    float4 ae0 = ae4[0], ae1 = ae4[1];
    const float4* as4 = (const float4*)(g_asrc + (size_t)src * HEADS);
    const float4* ad4 = (const float4*)(g_adst + (size_t)dst * HEADS);
    float4 as0 = as4[0], as1 = as4[1];
    float4 ad0 = ad4[0], ad1 = ad4[1];

    float a[HEADS];
    a[0] = as0.x + ad0.x + ae0.x;
    a[1] = as0.y + ad0.y + ae0.y;
    a[2] = as0.z + ad0.z + ae0.z;
    a[3] = as0.w + ad0.w + ae0.w;
    a[4] = as1.x + ad1.x + ae1.x;
    a[5] = as1.y + ad1.y + ae1.y;
    a[6] = as1.z + ad1.z + ae1.z;
    a[7] = as1.w + ad1.w + ae1.w;

    #pragma unroll
    for (int h = 0; h < HEADS; h++) {
        float al = a[h];
        al = (al > 0.f) ? al : 0.2f * al;   // LeakyReLU
        a[h] = __expf(al);                  // softmax is shift-invariant
    }
    int pos = atomicAdd(&g_cur[dst], 1);    // fused CSR slot reservation
    g_csr_src[pos] = src;
    float4* out = (float4*)(g_ea + (size_t)pos * HEADS);
    out[0] = make_float4(a[0], a[1], a[2], a[3]);
    out[1] = make_float4(a[4], a[5], a[6], a[7]);
}

// -------- aggregate: 1 warp/node, batched index loads, bf16 gather, LN ------
__global__ __launch_bounds__(256) void aggregate(const float* __restrict__ x,
                                                 const float* __restrict__ bias,
                                                 const float* __restrict__ gamma,
                                                 const float* __restrict__ beta,
                                                 float* __restrict__ out) {
    int node = blockIdx.x * 8 + (threadIdx.x >> 5);
    int lane = threadIdx.x & 31;
    if (node >= NN) return;
    int start = g_start[node];
    int deg   = g_deg[node];
    int myhead = lane >> 2;          // channels lane*8 .. lane*8+7 are all in this head
    int epair = myhead >> 1;         // ea float2 pair index for my head

    float accf[8];
    #pragma unroll
    for (int k = 0; k < 8; k++) accf[k] = 0.f;
    float2 den2 = make_float2(0.f, 0.f);   // heads (lane&3)*2, +1

    int i0 = 0;
    for (; i0 + 8 <= deg; i0 += 8) {
        int p0 = start + i0;
        int srcs = (lane < 8) ? g_csr_src[p0 + lane] : 0;
        float2 eav = *(const float2*)(g_ea + (size_t)(p0 + (lane >> 2)) * HEADS + (lane & 3) * 2);
        den2.x += eav.x;
        den2.y += eav.y;
        #pragma unroll
        for (int j = 0; j < 8; j++) {
            int src = __shfl_sync(0xffffffffu, srcs, j);
            float ex = __shfl_sync(0xffffffffu, eav.x, j * 4 + epair);
            float ey = __shfl_sync(0xffffffffu, eav.y, j * 4 + epair);
            float eh = (myhead & 1) ? ey : ex;
            uint4 v = *(const uint4*)(g_xpb + (size_t)src * HID + lane * 8);
            float2 f0 = __bfloat1622float2(*(__nv_bfloat162*)&v.x);
            float2 f1 = __bfloat1622float2(*(__nv_bfloat162*)&v.y);
            float2 f2 = __bfloat1622float2(*(__nv_bfloat162*)&v.z);
            float2 f3 = __bfloat1622float2(*(__nv_bfloat162*)&v.w);
            accf[0] += eh * f0.x; accf[1] += eh * f0.y;
            accf[2] += eh * f1.x; accf[3] += eh * f1.y;
            accf[4] += eh * f2.x; accf[5] += eh * f2.y;
            accf[6] += eh * f3.x; accf[7] += eh * f3.y;
        }
    }
    if (i0 < deg) {
        int rem = deg - i0;
        int p0 = start + i0;
        int srcs = (lane < rem && lane < 8) ? g_csr_src[p0 + lane] : 0;
        float2 eav = make_float2(0.f, 0.f);
        if ((lane >> 2) < rem)
            eav = *(const float2*)(g_ea + (size_t)(p0 + (lane >> 2)) * HEADS + (lane & 3) * 2);
        den2.x += eav.x;
        den2.y += eav.y;
        for (int j = 0; j < rem; j++) {
            int src = __shfl_sync(0xffffffffu, srcs, j);
            float ex = __shfl_sync(0xffffffffu, eav.x, j * 4 + epair);
            float ey = __shfl_sync(0xffffffffu, eav.y, j * 4 + epair);
            float eh = (myhead & 1) ? ey : ex;
            uint4 v = *(const uint4*)(g_xpb + (size_t)src * HID + lane * 8);
            float2 f0 = __bfloat1622float2(*(__nv_bfloat162*)&v.x);
            float2 f1 = __bfloat1622float2(*(__nv_bfloat162*)&v.y);
            float2 f2 = __bfloat1622float2(*(__nv_bfloat162*)&v.z);
            float2 f3 = __bfloat1622float2(*(__nv_bfloat162*)&v.w);
            accf[0] += eh * f0.x; accf[1] += eh * f0.y;
            accf[2] += eh * f1.x; accf[3] += eh * f1.y;
            accf[4] += eh * f2.x; accf[5] += eh * f2.y;
            accf[6] += eh * f3.x; accf[7] += eh * f3.y;
        }
    }

    // den: reduce over edge-slot lane bits (2,3,4); lanes grouped by (lane&3)
    #pragma unroll
    for (int o = 4; o < 32; o <<= 1) {
        den2.x += __shfl_xor_sync(0xffffffffu, den2.x, o);
        den2.y += __shfl_xor_sync(0xffffffffu, den2.y, o);
    }
    float dx = __shfl_sync(0xffffffffu, den2.x, epair);  // head myhead&~1
    float dy = __shfl_sync(0xffffffffu, den2.y, epair);  // head myhead|1
    float den = (myhead & 1) ? dy : dx;
    float inv = 1.f / (den + 1e-16f);

    // residual + bias
    const float4* x4 = (const float4*)(x + (size_t)node * HID + lane * 8);
    const float4* b4 = (const float4*)(bias + lane * 8);
    float4 xa = x4[0], xb = x4[1];
    float4 ba = b4[0], bb = b4[1];
    float va[8];
    va[0] = xa.x + accf[0] * inv + ba.x;
    va[1] = xa.y + accf[1] * inv + ba.y;
    va[2] = xa.z + accf[2] * inv + ba.z;
    va[3] = xa.w + accf[3] * inv + ba.w;
    va[4] = xb.x + accf[4] * inv + bb.x;
    va[5] = xb.y + accf[5] * inv + bb.y;
    va[6] = xb.z + accf[6] * inv + bb.z;
    va[7] = xb.w + accf[7] * inv + bb.w;

    float s = 0.f, q = 0.f;
    #pragma unroll
    for (int k = 0; k < 8; k++) { s += va[k]; q += va[k] * va[k]; }
    #pragma unroll
    for (int o = 16; o > 0; o >>= 1) {
        s += __shfl_xor_sync(0xffffffffu, s, o);
        q += __shfl_xor_sync(0xffffffffu, q, o);
    }
    float mu = s * (1.f / HID);
    float var = q * (1.f / HID) - mu * mu;
    float rstd = rsqrtf(var + 1e-5f);

    const float4* g4 = (const float4*)(gamma + lane * 8);
    const float4* e4 = (const float4*)(beta + lane * 8);
    float4 ga = g4[0], gb = g4[1];
    float4 be = e4[0], bf = e4[1];
    float4 oa, ob;
    oa.x = (va[0] - mu) * rstd * ga.x + be.x;
    oa.y = (va[1] - mu) * rstd * ga.y + be.y;
    oa.z = (va[2] - mu) * rstd * ga.z + be.z;
    oa.w = (va[3] - mu) * rstd * ga.w + be.w;
    ob.x = (va[4] - mu) * rstd * gb.x + bf.x;
    ob.y = (va[5] - mu) * rstd * gb.y + bf.y;
    ob.z = (va[6] - mu) * rstd * gb.z + bf.z;
    ob.w = (va[7] - mu) * rstd * gb.w + bf.w;

    float4* o4 = (float4*)(out + (size_t)node * HID + lane * 8);
    o4[0] = oa;
    o4[1] = ob;
}

// ---------------- launch: fork CSR+a_edge chain onto a side stream ---------
extern "C" void kernel_launch(void* const* d_in, const int* in_sizes, int n_in,
                              void* d_out, int out_size) {
    const float* x        = (const float*)d_in[0];
    const int*   ei       = (const int*)  d_in[1];
    const float* eattr    = (const float*)d_in[2];
    const float* W        = (const float*)d_in[3];
    const float* W_e      = (const float*)d_in[4];
    const float* att_src  = (const float*)d_in[5];
    const float* att_dst  = (const float*)d_in[6];
    const float* att_edge = (const float*)d_in[7];
    const float* bias     = (const float*)d_in[8];
    const float* gamma    = (const float*)d_in[9];
    const float* beta     = (const float*)d_in[10];
    float* out = (float*)d_out;

    cudaFuncSetAttribute(gemm_mma, cudaFuncAttributeMaxDynamicSharedMemorySize, SM_SZ);

    // Fresh handles each call (never destroyed: destroying mid-capture would
    // invalidate the graph; a few host-side handles per host invocation only).
    cudaStream_t side;
    cudaStreamCreateWithFlags(&side, cudaStreamNonBlocking);
    cudaEvent_t evFork, evJoin;
    cudaEventCreateWithFlags(&evFork, cudaEventDisableTiming);
    cudaEventCreateWithFlags(&evJoin, cudaEventDisableTiming);

    // fork
    cudaEventRecord(evFork, 0);
    cudaStreamWaitEvent(side, evFork, 0);

    // side branch: CSR build + watt fold + a_edge pass (independent of GEMM)
    zero_deg<<<(NN + 255) / 256, 256, 0, side>>>();
    compute_watt<<<1, EDIM * HEADS, 0, side>>>(W_e, att_edge);
    count_deg<<<(EE + 255) / 256, 256, 0, side>>>(ei);
    reserve_csr<<<(NN + 255) / 256, 256, 0, side>>>();
    edge_aedge<<<EE / EPB, EPB, 0, side>>>(eattr);

    // main branch: converts + tensor GEMM (+ fused node_att)
    convert_x<<<(NN * HID / 4 + 255) / 256, 256>>>(x);
    convert_w<<<(HID * HID + 255) / 256, 256>>>(W);
    dim3 ggrid(HID / 64, (NN + 127) / 128);
    gemm_mma<<<ggrid, 256, SM_SZ>>>(att_src, att_dst);

    // join: edge_scatter needs both branches
    cudaEventRecord(evJoin, side);
    cudaStreamWaitEvent(0, evJoin, 0);

    edge_scatter<<<(EE + 255) / 256, 256>>>(ei);
    aggregate<<<(NN + 7) / 8, 256>>>(x, bias, gamma, beta, out);
}